// round 2
// baseline (speedup 1.0000x reference)
#include <cuda_runtime.h>
#include <math.h>

// ---------------- problem constants ----------------
#define TOK    8192      // 4 * 2048 tokens
#define DIM    1024
#define INNER  1024
#define QKVN   3072
#define MLPD   4096
#define NH     16
#define DH     64
#define SEQ    2048
#define BATCH  4

// ---------------- device scratch (module-load allocated, no cudaMalloc) ----------------
__device__ float g_ln  [TOK * DIM];    // LN output (reused for ln1 and ln2)
__device__ float g_qkv [TOK * QKVN];   // qkv projection
__device__ float g_attn[TOK * INNER];  // attention output (pre out-proj)
__device__ float g_x2  [TOK * DIM];    // residual after attention
__device__ float g_mlp [TOK * MLPD];   // gelu(h @ w1 + b1)

// ---------------- LayerNorm: one block per row ----------------
__global__ void __launch_bounds__(256)
ln_kernel(const float* __restrict__ x, const float* __restrict__ gam,
          const float* __restrict__ bet, float* __restrict__ out)
{
    int row = blockIdx.x;
    int t = threadIdx.x;                       // 256 threads, DIM/4 = 256 float4
    const float4* xr = reinterpret_cast<const float4*>(x + (size_t)row * DIM);
    float4 v = xr[t];
    float s  = v.x + v.y + v.z + v.w;
    float sq = v.x*v.x + v.y*v.y + v.z*v.z + v.w*v.w;
    #pragma unroll
    for (int o = 16; o > 0; o >>= 1) {
        s  += __shfl_down_sync(0xffffffffu, s,  o);
        sq += __shfl_down_sync(0xffffffffu, sq, o);
    }
    __shared__ float ss[8], sqs[8];
    __shared__ float s_mu, s_rstd;
    int w = t >> 5, l = t & 31;
    if (l == 0) { ss[w] = s; sqs[w] = sq; }
    __syncthreads();
    if (t == 0) {
        float ts = 0.f, tq = 0.f;
        #pragma unroll
        for (int i = 0; i < 8; i++) { ts += ss[i]; tq += sqs[i]; }
        float mu  = ts * (1.0f / DIM);
        float var = tq * (1.0f / DIM) - mu * mu;
        s_mu = mu;
        s_rstd = rsqrtf(var + 1e-5f);
    }
    __syncthreads();
    float mu = s_mu, r = s_rstd;
    float4 g4 = reinterpret_cast<const float4*>(gam)[t];
    float4 b4 = reinterpret_cast<const float4*>(bet)[t];
    float4 o4;
    o4.x = (v.x - mu) * r * g4.x + b4.x;
    o4.y = (v.y - mu) * r * g4.y + b4.y;
    o4.z = (v.z - mu) * r * g4.z + b4.z;
    o4.w = (v.w - mu) * r * g4.w + b4.w;
    reinterpret_cast<float4*>(out + (size_t)row * DIM)[t] = o4;
}

// ---------------- SGEMM 128x128x16, 256 threads, 8x8 per thread ----------------
// C[M,N] = A[M,K] @ B[K,N] (+bias) (gelu?) (+res)
__device__ __forceinline__ float gelu_exact(float x) {
    return 0.5f * x * (1.0f + erff(x * 0.7071067811865475f));
}

__global__ void __launch_bounds__(256)
gemm_kernel(const float* __restrict__ A, const float* __restrict__ B,
            const float* __restrict__ bias, const float* __restrict__ res,
            float* __restrict__ C, int M, int N, int K, int gelu_flag)
{
    const int BM = 128, BN = 128, BK = 16;
    __shared__ float As[BK][BM];   // transposed A tile
    __shared__ float Bs[BK][BN];

    int tid = threadIdx.x;
    int tx = tid & 15, ty = tid >> 4;
    int m0 = blockIdx.y * BM;
    int n0 = blockIdx.x * BN;

    float acc[8][8];
    #pragma unroll
    for (int i = 0; i < 8; i++)
        #pragma unroll
        for (int j = 0; j < 8; j++) acc[i][j] = 0.f;

    for (int k0 = 0; k0 < K; k0 += BK) {
        // load A tile: 512 float4, each thread 2
        #pragma unroll
        for (int u = 0; u < 2; u++) {
            int f = tid * 2 + u;          // 0..511
            int row = f >> 2;             // 0..127
            int kq  = (f & 3) << 2;       // 0,4,8,12
            float4 a = *reinterpret_cast<const float4*>(&A[(size_t)(m0 + row) * K + k0 + kq]);
            As[kq + 0][row] = a.x; As[kq + 1][row] = a.y;
            As[kq + 2][row] = a.z; As[kq + 3][row] = a.w;
        }
        // load B tile: 512 float4
        #pragma unroll
        for (int u = 0; u < 2; u++) {
            int f = tid * 2 + u;
            int kr = f >> 5;              // 0..15
            int nq = (f & 31) << 2;       // 0..124
            *reinterpret_cast<float4*>(&Bs[kr][nq]) =
                *reinterpret_cast<const float4*>(&B[(size_t)(k0 + kr) * N + n0 + nq]);
        }
        __syncthreads();

        #pragma unroll
        for (int kk = 0; kk < BK; kk++) {
            float ar[8], br[8];
            *reinterpret_cast<float4*>(&ar[0]) = *reinterpret_cast<float4*>(&As[kk][ty * 8]);
            *reinterpret_cast<float4*>(&ar[4]) = *reinterpret_cast<float4*>(&As[kk][ty * 8 + 4]);
            *reinterpret_cast<float4*>(&br[0]) = *reinterpret_cast<float4*>(&Bs[kk][tx * 8]);
            *reinterpret_cast<float4*>(&br[4]) = *reinterpret_cast<float4*>(&Bs[kk][tx * 8 + 4]);
            #pragma unroll
            for (int i = 0; i < 8; i++)
                #pragma unroll
                for (int j = 0; j < 8; j++)
                    acc[i][j] += ar[i] * br[j];
        }
        __syncthreads();
    }

    // epilogue
    #pragma unroll
    for (int i = 0; i < 8; i++) {
        int m = m0 + ty * 8 + i;
        #pragma unroll
        for (int j = 0; j < 8; j += 4) {
            int n = n0 + tx * 8 + j;
            float4 c;
            c.x = acc[i][j]; c.y = acc[i][j + 1]; c.z = acc[i][j + 2]; c.w = acc[i][j + 3];
            if (bias) {
                const float4 bb = *reinterpret_cast<const float4*>(&bias[n]);
                c.x += bb.x; c.y += bb.y; c.z += bb.z; c.w += bb.w;
            }
            if (gelu_flag) {
                c.x = gelu_exact(c.x); c.y = gelu_exact(c.y);
                c.z = gelu_exact(c.z); c.w = gelu_exact(c.w);
            }
            if (res) {
                const float4 r4 = *reinterpret_cast<const float4*>(&res[(size_t)m * N + n]);
                c.x += r4.x; c.y += r4.y; c.z += r4.z; c.w += r4.w;
            }
            *reinterpret_cast<float4*>(&C[(size_t)m * N + n]) = c;
        }
    }
}

// ---------------- flash attention: 64-query tile per block ----------------
#define SD 68                         // padded row stride (floats), 16B-aligned
#define ATTN_SMEM ((4 * 64 * SD + 3 * 64) * sizeof(float))

__global__ void __launch_bounds__(256)
attn_kernel(const float* __restrict__ qkv, float* __restrict__ out)
{
    extern __shared__ float sm[];
    float* Qs = sm;                   // 64 x SD
    float* Ks = Qs + 64 * SD;
    float* Vs = Ks + 64 * SD;
    float* Ss = Vs + 64 * SD;
    float* m_s  = Ss + 64 * SD;       // 64
    float* l_s  = m_s + 64;           // 64
    float* al_s = l_s + 64;           // 64

    int tid = threadIdx.x;
    int tx = tid & 15, ty = tid >> 4;
    int qt = blockIdx.x;              // query tile 0..31
    int h  = blockIdx.y;              // head
    int b  = blockIdx.z;              // batch

    int row0 = b * SEQ + qt * 64;
    const float* qbase = qkv + (size_t)row0 * QKVN + h * DH;
    const float* kbase = qkv + (size_t)(b * SEQ) * QKVN + INNER     + h * DH;
    const float* vbase = qkv + (size_t)(b * SEQ) * QKVN + 2 * INNER + h * DH;

    // load Q tile (scaled by 1/sqrt(64))
    for (int f = tid; f < 64 * 16; f += 256) {
        int r = f >> 4, dq = (f & 15) << 2;
        float4 q4 = *reinterpret_cast<const float4*>(&qbase[(size_t)r * QKVN + dq]);
        float4 s4 = { q4.x * 0.125f, q4.y * 0.125f, q4.z * 0.125f, q4.w * 0.125f };
        *reinterpret_cast<float4*>(&Qs[r * SD + dq]) = s4;
    }
    if (tid < 64) { m_s[tid] = -1e30f; l_s[tid] = 0.f; }

    float o[4][4];
    #pragma unroll
    for (int i = 0; i < 4; i++)
        #pragma unroll
        for (int j = 0; j < 4; j++) o[i][j] = 0.f;

    for (int kt = 0; kt < SEQ / 64; kt++) {
        __syncthreads();  // previous tile's Ss/Vs fully consumed
        for (int f = tid; f < 64 * 16; f += 256) {
            int r = f >> 4, dq = (f & 15) << 2;
            size_t off = (size_t)(kt * 64 + r) * QKVN + dq;
            *reinterpret_cast<float4*>(&Ks[r * SD + dq]) =
                *reinterpret_cast<const float4*>(&kbase[off]);
            *reinterpret_cast<float4*>(&Vs[r * SD + dq]) =
                *reinterpret_cast<const float4*>(&vbase[off]);
        }
        __syncthreads();

        // S = Q @ K^T  (4x4 microtile per thread)
        float s[4][4];
        #pragma unroll
        for (int i = 0; i < 4; i++)
            #pragma unroll
            for (int j = 0; j < 4; j++) s[i][j] = 0.f;

        #pragma unroll 4
        for (int d = 0; d < 64; d += 4) {
            float4 qf[4], kf[4];
            #pragma unroll
            for (int i = 0; i < 4; i++)
                qf[i] = *reinterpret_cast<float4*>(&Qs[(ty * 4 + i) * SD + d]);
            #pragma unroll
            for (int j = 0; j < 4; j++)
                kf[j] = *reinterpret_cast<float4*>(&Ks[(tx * 4 + j) * SD + d]);
            #pragma unroll
            for (int i = 0; i < 4; i++)
                #pragma unroll
                for (int j = 0; j < 4; j++)
                    s[i][j] += qf[i].x * kf[j].x + qf[i].y * kf[j].y
                             + qf[i].z * kf[j].z + qf[i].w * kf[j].w;
        }
        #pragma unroll
        for (int i = 0; i < 4; i++)
            #pragma unroll
            for (int j = 0; j < 4; j++)
                Ss[(ty * 4 + i) * SD + tx * 4 + j] = s[i][j];
        __syncthreads();

        // online softmax row update (64 threads, one per query row)
        if (tid < 64) {
            int q = tid;
            float mold = m_s[q];
            float mx = mold;
            float* srow = &Ss[q * SD];
            #pragma unroll 4
            for (int k = 0; k < 64; k += 4) {
                float4 v4 = *reinterpret_cast<float4*>(&srow[k]);
                mx = fmaxf(mx, fmaxf(fmaxf(v4.x, v4.y), fmaxf(v4.z, v4.w)));
            }
            float alpha = __expf(mold - mx);
            float sum = 0.f;
            #pragma unroll 4
            for (int k = 0; k < 64; k += 4) {
                float4 v4 = *reinterpret_cast<float4*>(&srow[k]);
                v4.x = __expf(v4.x - mx); v4.y = __expf(v4.y - mx);
                v4.z = __expf(v4.z - mx); v4.w = __expf(v4.w - mx);
                sum += v4.x + v4.y + v4.z + v4.w;
                *reinterpret_cast<float4*>(&srow[k]) = v4;
            }
            l_s[q]  = l_s[q] * alpha + sum;
            m_s[q]  = mx;
            al_s[q] = alpha;
        }
        __syncthreads();

        // rescale O, accumulate P @ V
        float al[4];
        #pragma unroll
        for (int i = 0; i < 4; i++) al[i] = al_s[ty * 4 + i];
        #pragma unroll
        for (int i = 0; i < 4; i++)
            #pragma unroll
            for (int j = 0; j < 4; j++) o[i][j] *= al[i];

        #pragma unroll 8
        for (int k = 0; k < 64; k++) {
            float p[4];
            #pragma unroll
            for (int i = 0; i < 4; i++) p[i] = Ss[(ty * 4 + i) * SD + k];
            float4 v4 = *reinterpret_cast<float4*>(&Vs[k * SD + tx * 4]);
            #pragma unroll
            for (int i = 0; i < 4; i++) {
                o[i][0] += p[i] * v4.x; o[i][1] += p[i] * v4.y;
                o[i][2] += p[i] * v4.z; o[i][3] += p[i] * v4.w;
            }
        }
    }

    // write O / l
    #pragma unroll
    for (int i = 0; i < 4; i++) {
        int q = ty * 4 + i;
        float inv = 1.0f / l_s[q];
        float4 o4 = { o[i][0] * inv, o[i][1] * inv, o[i][2] * inv, o[i][3] * inv };
        *reinterpret_cast<float4*>(&out[(size_t)(row0 + q) * INNER + h * DH + tx * 4]) = o4;
    }
}

// ---------------- launch ----------------
extern "C" void kernel_launch(void* const* d_in, const int* in_sizes, int n_in,
                              void* d_out, int out_size)
{
    const float* x     = (const float*)d_in[0];
    const float* ln1_g = (const float*)d_in[1];
    const float* ln1_b = (const float*)d_in[2];
    const float* w_qkv = (const float*)d_in[3];
    const float* w_out = (const float*)d_in[4];
    const float* b_out = (const float*)d_in[5];
    const float* ln2_g = (const float*)d_in[6];
    const float* ln2_b = (const float*)d_in[7];
    const float* w1    = (const float*)d_in[8];
    const float* b1    = (const float*)d_in[9];
    const float* w2    = (const float*)d_in[10];
    const float* b2    = (const float*)d_in[11];
    float* out = (float*)d_out;

    float *ln, *qkv, *attn, *x2, *mlp;
    cudaGetSymbolAddress((void**)&ln,   g_ln);
    cudaGetSymbolAddress((void**)&qkv,  g_qkv);
    cudaGetSymbolAddress((void**)&attn, g_attn);
    cudaGetSymbolAddress((void**)&x2,   g_x2);
    cudaGetSymbolAddress((void**)&mlp,  g_mlp);

    cudaFuncSetAttribute(attn_kernel, cudaFuncAttributeMaxDynamicSharedMemorySize,
                         (int)ATTN_SMEM);

    // 1. h = LN1(x)
    ln_kernel<<<TOK, 256>>>(x, ln1_g, ln1_b, ln);
    // 2. qkv = h @ w_qkv
    gemm_kernel<<<dim3(QKVN / 128, TOK / 128), 256>>>(
        ln, w_qkv, nullptr, nullptr, qkv, TOK, QKVN, DIM, 0);
    // 3. attention
    attn_kernel<<<dim3(SEQ / 64, NH, BATCH), 256, ATTN_SMEM>>>(qkv, attn);
    // 4. x2 = attn @ w_out + b_out + x
    gemm_kernel<<<dim3(DIM / 128, TOK / 128), 256>>>(
        attn, w_out, b_out, x, x2, TOK, DIM, INNER, 0);
    // 5. h = LN2(x2)
    ln_kernel<<<TOK, 256>>>(x2, ln2_g, ln2_b, ln);
    // 6. mlp = gelu(h @ w1 + b1)
    gemm_kernel<<<dim3(MLPD / 128, TOK / 128), 256>>>(
        ln, w1, b1, nullptr, mlp, TOK, MLPD, DIM, 1);
    // 7. out = mlp @ w2 + b2 + x2
    gemm_kernel<<<dim3(DIM / 128, TOK / 128), 256>>>(
        mlp, w2, b2, x2, out, TOK, DIM, MLPD, 0);
}

// round 4
// speedup vs baseline: 1.5991x; 1.5991x over previous
#include <cuda_runtime.h>
#include <cuda_bf16.h>
#include <math.h>
#include <stdint.h>

// ---------------- problem constants ----------------
#define TOK    8192
#define DIM    1024
#define INNER  1024
#define QKVN   3072
#define MLPD   4096
#define NH     16
#define DH     64
#define SEQ    2048
#define BATCH  4

// ---------------- device scratch ----------------
__device__ __nv_bfloat16 g_wqkv_h[DIM * QKVN];   // transposed [N,K]
__device__ __nv_bfloat16 g_wqkv_l[DIM * QKVN];
__device__ __nv_bfloat16 g_wout_h[INNER * DIM];
__device__ __nv_bfloat16 g_wout_l[INNER * DIM];
__device__ __nv_bfloat16 g_w1_h[DIM * MLPD];
__device__ __nv_bfloat16 g_w1_l[DIM * MLPD];
__device__ __nv_bfloat16 g_w2_h[MLPD * DIM];
__device__ __nv_bfloat16 g_w2_l[MLPD * DIM];
__device__ __nv_bfloat16 g_ah[TOK * DIM];        // activation hi/lo
__device__ __nv_bfloat16 g_al[TOK * DIM];
__device__ __nv_bfloat16 g_bh[TOK * MLPD];       // mlp intermediate hi/lo
__device__ __nv_bfloat16 g_bl[TOK * MLPD];
__device__ float g_qkv[TOK * QKVN];
__device__ float g_x2 [TOK * DIM];

// ---------------- small helpers ----------------
__device__ __forceinline__ uint32_t smem_u32(const void* p) {
    uint32_t a;
    asm("{ .reg .u64 t; cvta.to.shared.u64 t, %1; cvt.u32.u64 %0, t; }" : "=r"(a) : "l"(p));
    return a;
}

__device__ __forceinline__ void split_bf16(float v, unsigned short& h, unsigned short& l) {
    __nv_bfloat16 hb = __float2bfloat16(v);
    float hf = __bfloat162float(hb);
    __nv_bfloat16 lb = __float2bfloat16(v - hf);
    h = __bfloat16_as_ushort(hb);
    l = __bfloat16_as_ushort(lb);
}

__device__ __forceinline__ void cpa16(uint32_t dst, const void* src) {
    asm volatile("cp.async.cg.shared.global [%0], [%1], 16;" :: "r"(dst), "l"(src));
}
__device__ __forceinline__ void cpa_commit() { asm volatile("cp.async.commit_group;" ::: "memory"); }

__device__ __forceinline__ void ldm_x4(uint32_t* r, uint32_t addr) {
    asm volatile("ldmatrix.sync.aligned.m8n8.x4.shared.b16 {%0,%1,%2,%3}, [%4];"
                 : "=r"(r[0]), "=r"(r[1]), "=r"(r[2]), "=r"(r[3]) : "r"(addr));
}

__device__ __forceinline__ void mma_bf16(float* c, const uint32_t* a, const uint32_t* b) {
    asm volatile(
        "mma.sync.aligned.m16n8k16.row.col.f32.bf16.bf16.f32 "
        "{%0,%1,%2,%3}, {%4,%5,%6,%7}, {%8,%9}, {%0,%1,%2,%3};"
        : "+f"(c[0]), "+f"(c[1]), "+f"(c[2]), "+f"(c[3])
        : "r"(a[0]), "r"(a[1]), "r"(a[2]), "r"(a[3]), "r"(b[0]), "r"(b[1]));
}

__device__ __forceinline__ float gelu_exact(float x) {
    return 0.5f * x * (1.0f + erff(x * 0.7071067811865475f));
}

// ---------------- weight convert + transpose: fp32 [K,N] -> bf16 hi/lo [N,K] ----------------
__global__ void __launch_bounds__(256)
wconv_kernel(const float* __restrict__ W, __nv_bfloat16* __restrict__ Th,
             __nv_bfloat16* __restrict__ Tl, int K, int N)
{
    __shared__ float tile[32][33];
    int n0 = blockIdx.x * 32, k0 = blockIdx.y * 32;
    int tx = threadIdx.x & 31, ty = threadIdx.x >> 5;
    #pragma unroll
    for (int i = 0; i < 4; i++)
        tile[ty + i * 8][tx] = W[(size_t)(k0 + ty + i * 8) * N + n0 + tx];
    __syncthreads();
    #pragma unroll
    for (int i = 0; i < 4; i++) {
        float v = tile[tx][ty + i * 8];
        unsigned short h, l;
        split_bf16(v, h, l);
        size_t o = (size_t)(n0 + ty + i * 8) * K + k0 + tx;
        Th[o] = __ushort_as_bfloat16(h);
        Tl[o] = __ushort_as_bfloat16(l);
    }
}

// ---------------- LayerNorm -> bf16 hi/lo ----------------
__global__ void __launch_bounds__(256)
ln_kernel(const float* __restrict__ x, const float* __restrict__ gam,
          const float* __restrict__ bet, __nv_bfloat16* __restrict__ oh,
          __nv_bfloat16* __restrict__ ol)
{
    int row = blockIdx.x;
    int t = threadIdx.x;
    const float4* xr = reinterpret_cast<const float4*>(x + (size_t)row * DIM);
    float4 v = xr[t];
    float s  = v.x + v.y + v.z + v.w;
    float sq = v.x*v.x + v.y*v.y + v.z*v.z + v.w*v.w;
    #pragma unroll
    for (int o = 16; o > 0; o >>= 1) {
        s  += __shfl_down_sync(0xffffffffu, s,  o);
        sq += __shfl_down_sync(0xffffffffu, sq, o);
    }
    __shared__ float ss[8], sqs[8];
    __shared__ float s_mu, s_rstd;
    int w = t >> 5, l = t & 31;
    if (l == 0) { ss[w] = s; sqs[w] = sq; }
    __syncthreads();
    if (t == 0) {
        float ts = 0.f, tq = 0.f;
        #pragma unroll
        for (int i = 0; i < 8; i++) { ts += ss[i]; tq += sqs[i]; }
        float mu  = ts * (1.0f / DIM);
        float var = tq * (1.0f / DIM) - mu * mu;
        s_mu = mu; s_rstd = rsqrtf(var + 1e-5f);
    }
    __syncthreads();
    float mu = s_mu, r = s_rstd;
    float4 g4 = reinterpret_cast<const float4*>(gam)[t];
    float4 b4 = reinterpret_cast<const float4*>(bet)[t];
    float o0 = (v.x - mu) * r * g4.x + b4.x;
    float o1 = (v.y - mu) * r * g4.y + b4.y;
    float o2 = (v.z - mu) * r * g4.z + b4.z;
    float o3 = (v.w - mu) * r * g4.w + b4.w;
    ushort4 hu, lu;
    split_bf16(o0, hu.x, lu.x); split_bf16(o1, hu.y, lu.y);
    split_bf16(o2, hu.z, lu.z); split_bf16(o3, hu.w, lu.w);
    size_t idx = (size_t)row * DIM + t * 4;
    *reinterpret_cast<ushort4*>(oh + idx) = hu;
    *reinterpret_cast<ushort4*>(ol + idx) = lu;
}

// ---------------- HMMA bf16 hi/lo split GEMM ----------------
// C[M,N] = A[M,K] @ Bt[N,K]^T, fp32 accum. 128x128 tile, BK=32, 8 warps (4Mx2N).
// smem: per stage 4 matrices (Ah,Al,Bh,Bl) of 128 rows x 40 bf16 (stride 80B).
#define GSTRIDE  80                     // bytes per smem row (40 bf16, 32 used)
#define GMAT     (128 * GSTRIDE)        // 10240 B
#define GSTAGE   (4 * GMAT)             // 40960 B
#define GEMM_SMEM (2 * GSTAGE)          // 81920 B

__global__ void __launch_bounds__(256)
gemm_bf16_kernel(const __nv_bfloat16* __restrict__ Ah, const __nv_bfloat16* __restrict__ Al,
                 const __nv_bfloat16* __restrict__ Bh, const __nv_bfloat16* __restrict__ Bl,
                 const float* __restrict__ bias, const float* __restrict__ res,
                 float* __restrict__ Cf, __nv_bfloat16* __restrict__ Ch,
                 __nv_bfloat16* __restrict__ Cl, int M, int N, int K, int gelu_flag)
{
    extern __shared__ char smem[];
    uint32_t sb0 = smem_u32(smem);
    int tid = threadIdx.x;
    int wid = tid >> 5, lane = tid & 31;
    int warp_m = wid & 3, warp_n = wid >> 2;
    int m0 = blockIdx.y * 128, n0 = blockIdx.x * 128;

    // ---- load mapping: each thread loads 32B (2x16B) per matrix per stage ----
    int lrow = tid >> 1;                 // 0..127
    int lcol = (tid & 1) * 32;           // byte offset within 64B row
    uint32_t soff = (uint32_t)lrow * GSTRIDE + lcol;
    const char* gA_h = (const char*)(Ah + (size_t)(m0 + lrow) * K) + lcol;
    const char* gA_l = (const char*)(Al + (size_t)(m0 + lrow) * K) + lcol;
    const char* gB_h = (const char*)(Bh + (size_t)(n0 + lrow) * K) + lcol;
    const char* gB_l = (const char*)(Bl + (size_t)(n0 + lrow) * K) + lcol;

    float acc[2][8][4];
    #pragma unroll
    for (int i = 0; i < 2; i++)
        #pragma unroll
        for (int j = 0; j < 8; j++)
            #pragma unroll
            for (int q = 0; q < 4; q++) acc[i][j][q] = 0.f;

    int C = K >> 5;                      // chunks of 32 bf16 (64 B)

    // prefetch chunk 0 -> stage 0
    {
        uint32_t d = sb0 + soff;
        cpa16(d + 0 * GMAT, gA_h);      cpa16(d + 0 * GMAT + 16, gA_h + 16);
        cpa16(d + 1 * GMAT, gA_l);      cpa16(d + 1 * GMAT + 16, gA_l + 16);
        cpa16(d + 2 * GMAT, gB_h);      cpa16(d + 2 * GMAT + 16, gB_h + 16);
        cpa16(d + 3 * GMAT, gB_l);      cpa16(d + 3 * GMAT + 16, gB_l + 16);
        cpa_commit();
    }

    // ldmatrix address precompute (per-lane)
    int lg = lane & 7;                   // row within 8
    int sel = lane >> 3;                 // 0..3 -> matrix index
    // A tiles: base rows warp_m*32 + mt*16; mats: (r+ (sel&1)*8, kk*16 + (sel>>1)*8)
    uint32_t a_lane_off = (uint32_t)(lg + (sel & 1) * 8) * GSTRIDE + (uint32_t)(sel >> 1) * 16;
    // B pairs: base rows warp_n*64 + pair*16; mats: (r + (sel>>1)*8, kk*16 + (sel&1)*8)
    uint32_t b_lane_off = (uint32_t)(lg + (sel >> 1) * 8) * GSTRIDE + (uint32_t)(sel & 1) * 16;

    for (int c = 0; c < C; c++) {
        if (c + 1 < C) {
            uint32_t d = sb0 + ((c + 1) & 1) * GSTAGE + soff;
            size_t go = (size_t)(c + 1) * 64;
            cpa16(d + 0 * GMAT, gA_h + go);  cpa16(d + 0 * GMAT + 16, gA_h + go + 16);
            cpa16(d + 1 * GMAT, gA_l + go);  cpa16(d + 1 * GMAT + 16, gA_l + go + 16);
            cpa16(d + 2 * GMAT, gB_h + go);  cpa16(d + 2 * GMAT + 16, gB_h + go + 16);
            cpa16(d + 3 * GMAT, gB_l + go);  cpa16(d + 3 * GMAT + 16, gB_l + go + 16);
            cpa_commit();
            asm volatile("cp.async.wait_group 1;" ::: "memory");
        } else {
            asm volatile("cp.async.wait_group 0;" ::: "memory");
        }
        __syncthreads();

        uint32_t st = sb0 + (c & 1) * GSTAGE;
        uint32_t aH = st + 0 * GMAT, aL = st + 1 * GMAT;
        uint32_t bH = st + 2 * GMAT, bL = st + 3 * GMAT;

        #pragma unroll
        for (int kk = 0; kk < 2; kk++) {
            uint32_t kb = (uint32_t)kk * 32;             // 16 bf16 = 32 B
            uint32_t afh[2][4], afl[2][4], bfh[8][2], bfl[8][2];
            #pragma unroll
            for (int mt = 0; mt < 2; mt++) {
                uint32_t ro = (uint32_t)(warp_m * 32 + mt * 16) * GSTRIDE + kb + a_lane_off;
                ldm_x4(afh[mt], aH + ro);
                ldm_x4(afl[mt], aL + ro);
            }
            #pragma unroll
            for (int pr = 0; pr < 4; pr++) {
                uint32_t ro = (uint32_t)(warp_n * 64 + pr * 16) * GSTRIDE + kb + b_lane_off;
                uint32_t th[4], tl[4];
                ldm_x4(th, bH + ro);
                ldm_x4(tl, bL + ro);
                bfh[pr * 2][0] = th[0]; bfh[pr * 2][1] = th[1];
                bfh[pr * 2 + 1][0] = th[2]; bfh[pr * 2 + 1][1] = th[3];
                bfl[pr * 2][0] = tl[0]; bfl[pr * 2][1] = tl[1];
                bfl[pr * 2 + 1][0] = tl[2]; bfl[pr * 2 + 1][1] = tl[3];
            }
            #pragma unroll
            for (int mt = 0; mt < 2; mt++)
                #pragma unroll
                for (int nt = 0; nt < 8; nt++) {
                    mma_bf16(acc[mt][nt], afh[mt], bfh[nt]);
                    mma_bf16(acc[mt][nt], afh[mt], bfl[nt]);
                    mma_bf16(acc[mt][nt], afl[mt], bfh[nt]);
                }
        }
        __syncthreads();
    }

    // ---- epilogue: acc regs -> global ----
    int g = lane >> 2, tig = lane & 3;
    #pragma unroll
    for (int mt = 0; mt < 2; mt++) {
        #pragma unroll
        for (int half = 0; half < 2; half++) {     // c0,c1 vs c2,c3 (row +8)
            int r = m0 + warp_m * 32 + mt * 16 + g + half * 8;
            #pragma unroll
            for (int nt = 0; nt < 8; nt++) {
                int cc = n0 + warp_n * 64 + nt * 8 + tig * 2;
                float v0 = acc[mt][nt][half * 2 + 0];
                float v1 = acc[mt][nt][half * 2 + 1];
                if (bias) {
                    v0 += bias[cc]; v1 += bias[cc + 1];
                }
                if (gelu_flag) { v0 = gelu_exact(v0); v1 = gelu_exact(v1); }
                size_t o = (size_t)r * N + cc;
                if (res) {
                    float2 r2 = *reinterpret_cast<const float2*>(res + o);
                    v0 += r2.x; v1 += r2.y;
                }
                if (Cf) {
                    float2 f2 = { v0, v1 };
                    *reinterpret_cast<float2*>(Cf + o) = f2;
                } else {
                    ushort2 hu, lu;
                    split_bf16(v0, hu.x, lu.x);
                    split_bf16(v1, hu.y, lu.y);
                    *reinterpret_cast<ushort2*>(Ch + o) = hu;
                    *reinterpret_cast<ushort2*>(Cl + o) = lu;
                }
            }
        }
    }
}

// ---------------- flash attention (fp32), outputs bf16 hi/lo ----------------
#define SD 68
#define ATTN_SMEM ((4 * 64 * SD + 3 * 64) * sizeof(float))

__global__ void __launch_bounds__(256)
attn_kernel(const float* __restrict__ qkv, __nv_bfloat16* __restrict__ oh,
            __nv_bfloat16* __restrict__ ol)
{
    extern __shared__ float sm[];
    float* Qs = sm;
    float* Ks = Qs + 64 * SD;
    float* Vs = Ks + 64 * SD;
    float* Ss = Vs + 64 * SD;
    float* m_s  = Ss + 64 * SD;
    float* l_s  = m_s + 64;
    float* al_s = l_s + 64;

    int tid = threadIdx.x;
    int tx = tid & 15, ty = tid >> 4;
    int qt = blockIdx.x, h = blockIdx.y, b = blockIdx.z;

    int row0 = b * SEQ + qt * 64;
    const float* qbase = qkv + (size_t)row0 * QKVN + h * DH;
    const float* kbase = qkv + (size_t)(b * SEQ) * QKVN + INNER     + h * DH;
    const float* vbase = qkv + (size_t)(b * SEQ) * QKVN + 2 * INNER + h * DH;

    for (int f = tid; f < 64 * 16; f += 256) {
        int r = f >> 4, dq = (f & 15) << 2;
        float4 q4 = *reinterpret_cast<const float4*>(&qbase[(size_t)r * QKVN + dq]);
        float4 s4 = { q4.x * 0.125f, q4.y * 0.125f, q4.z * 0.125f, q4.w * 0.125f };
        *reinterpret_cast<float4*>(&Qs[r * SD + dq]) = s4;
    }
    if (tid < 64) { m_s[tid] = -1e30f; l_s[tid] = 0.f; }

    float o[4][4];
    #pragma unroll
    for (int i = 0; i < 4; i++)
        #pragma unroll
        for (int j = 0; j < 4; j++) o[i][j] = 0.f;

    for (int kt = 0; kt < SEQ / 64; kt++) {
        __syncthreads();
        for (int f = tid; f < 64 * 16; f += 256) {
            int r = f >> 4, dq = (f & 15) << 2;
            size_t off = (size_t)(kt * 64 + r) * QKVN + dq;
            *reinterpret_cast<float4*>(&Ks[r * SD + dq]) =
                *reinterpret_cast<const float4*>(&kbase[off]);
            *reinterpret_cast<float4*>(&Vs[r * SD + dq]) =
                *reinterpret_cast<const float4*>(&vbase[off]);
        }
        __syncthreads();

        float s[4][4];
        #pragma unroll
        for (int i = 0; i < 4; i++)
            #pragma unroll
            for (int j = 0; j < 4; j++) s[i][j] = 0.f;

        #pragma unroll 4
        for (int d = 0; d < 64; d += 4) {
            float4 qf[4], kf[4];
            #pragma unroll
            for (int i = 0; i < 4; i++)
                qf[i] = *reinterpret_cast<float4*>(&Qs[(ty * 4 + i) * SD + d]);
            #pragma unroll
            for (int j = 0; j < 4; j++)
                kf[j] = *reinterpret_cast<float4*>(&Ks[(tx * 4 + j) * SD + d]);
            #pragma unroll
            for (int i = 0; i < 4; i++)
                #pragma unroll
                for (int j = 0; j < 4; j++)
                    s[i][j] += qf[i].x * kf[j].x + qf[i].y * kf[j].y
                             + qf[i].z * kf[j].z + qf[i].w * kf[j].w;
        }
        #pragma unroll
        for (int i = 0; i < 4; i++)
            #pragma unroll
            for (int j = 0; j < 4; j++)
                Ss[(ty * 4 + i) * SD + tx * 4 + j] = s[i][j];
        __syncthreads();

        if (tid < 64) {
            int q = tid;
            float mold = m_s[q];
            float mx = mold;
            float* srow = &Ss[q * SD];
            #pragma unroll 4
            for (int k = 0; k < 64; k += 4) {
                float4 v4 = *reinterpret_cast<float4*>(&srow[k]);
                mx = fmaxf(mx, fmaxf(fmaxf(v4.x, v4.y), fmaxf(v4.z, v4.w)));
            }
            float alpha = __expf(mold - mx);
            float sum = 0.f;
            #pragma unroll 4
            for (int k = 0; k < 64; k += 4) {
                float4 v4 = *reinterpret_cast<float4*>(&srow[k]);
                v4.x = __expf(v4.x - mx); v4.y = __expf(v4.y - mx);
                v4.z = __expf(v4.z - mx); v4.w = __expf(v4.w - mx);
                sum += v4.x + v4.y + v4.z + v4.w;
                *reinterpret_cast<float4*>(&srow[k]) = v4;
            }
            l_s[q]  = l_s[q] * alpha + sum;
            m_s[q]  = mx;
            al_s[q] = alpha;
        }
        __syncthreads();

        float al[4];
        #pragma unroll
        for (int i = 0; i < 4; i++) al[i] = al_s[ty * 4 + i];
        #pragma unroll
        for (int i = 0; i < 4; i++)
            #pragma unroll
            for (int j = 0; j < 4; j++) o[i][j] *= al[i];

        #pragma unroll 8
        for (int k = 0; k < 64; k++) {
            float p[4];
            #pragma unroll
            for (int i = 0; i < 4; i++) p[i] = Ss[(ty * 4 + i) * SD + k];
            float4 v4 = *reinterpret_cast<float4*>(&Vs[k * SD + tx * 4]);
            #pragma unroll
            for (int i = 0; i < 4; i++) {
                o[i][0] += p[i] * v4.x; o[i][1] += p[i] * v4.y;
                o[i][2] += p[i] * v4.z; o[i][3] += p[i] * v4.w;
            }
        }
    }

    #pragma unroll
    for (int i = 0; i < 4; i++) {
        int q = ty * 4 + i;
        float inv = 1.0f / l_s[q];
        float o0 = o[i][0] * inv, o1 = o[i][1] * inv;
        float o2 = o[i][2] * inv, o3 = o[i][3] * inv;
        ushort4 hu, lu;
        split_bf16(o0, hu.x, lu.x); split_bf16(o1, hu.y, lu.y);
        split_bf16(o2, hu.z, lu.z); split_bf16(o3, hu.w, lu.w);
        size_t idx = (size_t)(row0 + q) * INNER + h * DH + tx * 4;
        *reinterpret_cast<ushort4*>(oh + idx) = hu;
        *reinterpret_cast<ushort4*>(ol + idx) = lu;
    }
}

// ---------------- launch ----------------
extern "C" void kernel_launch(void* const* d_in, const int* in_sizes, int n_in,
                              void* d_out, int out_size)
{
    const float* x     = (const float*)d_in[0];
    const float* ln1_g = (const float*)d_in[1];
    const float* ln1_b = (const float*)d_in[2];
    const float* w_qkv = (const float*)d_in[3];
    const float* w_out = (const float*)d_in[4];
    const float* b_out = (const float*)d_in[5];
    const float* ln2_g = (const float*)d_in[6];
    const float* ln2_b = (const float*)d_in[7];
    const float* w1    = (const float*)d_in[8];
    const float* b1    = (const float*)d_in[9];
    const float* w2    = (const float*)d_in[10];
    const float* b2    = (const float*)d_in[11];
    float* out = (float*)d_out;

    __nv_bfloat16 *wqkv_h, *wqkv_l, *wout_h, *wout_l, *w1_h, *w1_l, *w2_h, *w2_l;
    __nv_bfloat16 *ah, *al, *bh, *bl;
    float *qkv, *x2;
    cudaGetSymbolAddress((void**)&wqkv_h, g_wqkv_h);
    cudaGetSymbolAddress((void**)&wqkv_l, g_wqkv_l);
    cudaGetSymbolAddress((void**)&wout_h, g_wout_h);
    cudaGetSymbolAddress((void**)&wout_l, g_wout_l);
    cudaGetSymbolAddress((void**)&w1_h,   g_w1_h);
    cudaGetSymbolAddress((void**)&w1_l,   g_w1_l);
    cudaGetSymbolAddress((void**)&w2_h,   g_w2_h);
    cudaGetSymbolAddress((void**)&w2_l,   g_w2_l);
    cudaGetSymbolAddress((void**)&ah,     g_ah);
    cudaGetSymbolAddress((void**)&al,     g_al);
    cudaGetSymbolAddress((void**)&bh,     g_bh);
    cudaGetSymbolAddress((void**)&bl,     g_bl);
    cudaGetSymbolAddress((void**)&qkv,    g_qkv);
    cudaGetSymbolAddress((void**)&x2,     g_x2);

    cudaFuncSetAttribute(gemm_bf16_kernel, cudaFuncAttributeMaxDynamicSharedMemorySize, GEMM_SMEM);
    cudaFuncSetAttribute(attn_kernel, cudaFuncAttributeMaxDynamicSharedMemorySize, (int)ATTN_SMEM);

    // weight split+transpose
    wconv_kernel<<<dim3(QKVN / 32, DIM / 32), 256>>>(w_qkv, wqkv_h, wqkv_l, DIM, QKVN);
    wconv_kernel<<<dim3(DIM / 32, INNER / 32), 256>>>(w_out, wout_h, wout_l, INNER, DIM);
    wconv_kernel<<<dim3(MLPD / 32, DIM / 32), 256>>>(w1, w1_h, w1_l, DIM, MLPD);
    wconv_kernel<<<dim3(DIM / 32, MLPD / 32), 256>>>(w2, w2_h, w2_l, MLPD, DIM);

    // 1. LN1 -> bf16 hi/lo
    ln_kernel<<<TOK, 256>>>(x, ln1_g, ln1_b, ah, al);
    // 2. qkv = h @ w_qkv (fp32 out)
    gemm_bf16_kernel<<<dim3(QKVN / 128, TOK / 128), 256, GEMM_SMEM>>>(
        ah, al, wqkv_h, wqkv_l, nullptr, nullptr, qkv, nullptr, nullptr,
        TOK, QKVN, DIM, 0);
    // 3. attention -> bf16 hi/lo
    attn_kernel<<<dim3(SEQ / 64, NH, BATCH), 256, ATTN_SMEM>>>(qkv, ah, al);
    // 4. x2 = attn @ w_out + b_out + x (fp32)
    gemm_bf16_kernel<<<dim3(DIM / 128, TOK / 128), 256, GEMM_SMEM>>>(
        ah, al, wout_h, wout_l, b_out, x, x2, nullptr, nullptr,
        TOK, DIM, INNER, 0);
    // 5. LN2 -> bf16 hi/lo
    ln_kernel<<<TOK, 256>>>(x2, ln2_g, ln2_b, ah, al);
    // 6. mlp = gelu(h @ w1 + b1) -> bf16 hi/lo
    gemm_bf16_kernel<<<dim3(MLPD / 128, TOK / 128), 256, GEMM_SMEM>>>(
        ah, al, w1_h, w1_l, b1, nullptr, nullptr, bh, bl,
        TOK, MLPD, DIM, 1);
    // 7. out = mlp @ w2 + b2 + x2 (fp32)
    gemm_bf16_kernel<<<dim3(DIM / 128, TOK / 128), 256, GEMM_SMEM>>>(
        bh, bl, w2_h, w2_l, b2, x2, out, nullptr, nullptr,
        TOK, DIM, MLPD, 0);
}

// round 5
// speedup vs baseline: 3.1152x; 1.9481x over previous
#include <cuda_runtime.h>
#include <cuda_bf16.h>
#include <math.h>
#include <stdint.h>

// ---------------- problem constants ----------------
#define TOK    8192
#define DIM    1024
#define INNER  1024
#define QKVN   3072
#define MLPD   4096
#define NH     16
#define DH     64
#define SEQ    2048
#define BATCH  4

// ---------------- device scratch ----------------
__device__ __nv_bfloat16 g_wqkv_h[DIM * QKVN];
__device__ __nv_bfloat16 g_wqkv_l[DIM * QKVN];
__device__ __nv_bfloat16 g_wout_h[INNER * DIM];
__device__ __nv_bfloat16 g_wout_l[INNER * DIM];
__device__ __nv_bfloat16 g_w1_h[DIM * MLPD];
__device__ __nv_bfloat16 g_w1_l[DIM * MLPD];
__device__ __nv_bfloat16 g_w2_h[MLPD * DIM];
__device__ __nv_bfloat16 g_w2_l[MLPD * DIM];
__device__ __nv_bfloat16 g_ah[TOK * DIM];        // activation hi/lo
__device__ __nv_bfloat16 g_al[TOK * DIM];
__device__ __nv_bfloat16 g_bh[TOK * MLPD];       // mlp intermediate hi/lo
__device__ __nv_bfloat16 g_bl[TOK * MLPD];
__device__ __nv_bfloat16 g_qh[TOK * QKVN];       // qkv hi/lo
__device__ __nv_bfloat16 g_ql[TOK * QKVN];
__device__ float g_x2 [TOK * DIM];

// ---------------- small helpers ----------------
__device__ __forceinline__ uint32_t smem_u32(const void* p) {
    uint32_t a;
    asm("{ .reg .u64 t; cvta.to.shared.u64 t, %1; cvt.u32.u64 %0, t; }" : "=r"(a) : "l"(p));
    return a;
}

__device__ __forceinline__ void split_bf16(float v, unsigned short& h, unsigned short& l) {
    __nv_bfloat16 hb = __float2bfloat16(v);
    float hf = __bfloat162float(hb);
    __nv_bfloat16 lb = __float2bfloat16(v - hf);
    h = __bfloat16_as_ushort(hb);
    l = __bfloat16_as_ushort(lb);
}

// split a pair (e0->low, e1->high) into hi/lo bf16x2 registers
__device__ __forceinline__ void split_pack2(float e0, float e1, uint32_t& hi, uint32_t& lo) {
    __nv_bfloat16 h0 = __float2bfloat16(e0), h1 = __float2bfloat16(e1);
    float r0 = e0 - __bfloat162float(h0);
    float r1 = e1 - __bfloat162float(h1);
    __nv_bfloat162 hh, ll;
    hh.x = h0; hh.y = h1;
    ll.x = __float2bfloat16(r0); ll.y = __float2bfloat16(r1);
    hi = *reinterpret_cast<uint32_t*>(&hh);
    lo = *reinterpret_cast<uint32_t*>(&ll);
}

__device__ __forceinline__ void cpa16(uint32_t dst, const void* src) {
    asm volatile("cp.async.cg.shared.global [%0], [%1], 16;" :: "r"(dst), "l"(src));
}
__device__ __forceinline__ void cpa_commit() { asm volatile("cp.async.commit_group;" ::: "memory"); }

__device__ __forceinline__ void ldm_x4(uint32_t* r, uint32_t addr) {
    asm volatile("ldmatrix.sync.aligned.m8n8.x4.shared.b16 {%0,%1,%2,%3}, [%4];"
                 : "=r"(r[0]), "=r"(r[1]), "=r"(r[2]), "=r"(r[3]) : "r"(addr));
}
__device__ __forceinline__ void ldm_x4_t(uint32_t* r, uint32_t addr) {
    asm volatile("ldmatrix.sync.aligned.m8n8.x4.trans.shared.b16 {%0,%1,%2,%3}, [%4];"
                 : "=r"(r[0]), "=r"(r[1]), "=r"(r[2]), "=r"(r[3]) : "r"(addr));
}

__device__ __forceinline__ void mma_bf16(float* c, const uint32_t* a, const uint32_t* b) {
    asm volatile(
        "mma.sync.aligned.m16n8k16.row.col.f32.bf16.bf16.f32 "
        "{%0,%1,%2,%3}, {%4,%5,%6,%7}, {%8,%9}, {%0,%1,%2,%3};"
        : "+f"(c[0]), "+f"(c[1]), "+f"(c[2]), "+f"(c[3])
        : "r"(a[0]), "r"(a[1]), "r"(a[2]), "r"(a[3]), "r"(b[0]), "r"(b[1]));
}

__device__ __forceinline__ float gelu_exact(float x) {
    return 0.5f * x * (1.0f + erff(x * 0.7071067811865475f));
}

// ---------------- weight convert + transpose: fp32 [K,N] -> bf16 hi/lo [N,K] ----------------
__global__ void __launch_bounds__(256)
wconv_kernel(const float* __restrict__ W, __nv_bfloat16* __restrict__ Th,
             __nv_bfloat16* __restrict__ Tl, int K, int N)
{
    __shared__ float tile[32][33];
    int n0 = blockIdx.x * 32, k0 = blockIdx.y * 32;
    int tx = threadIdx.x & 31, ty = threadIdx.x >> 5;
    #pragma unroll
    for (int i = 0; i < 4; i++)
        tile[ty + i * 8][tx] = W[(size_t)(k0 + ty + i * 8) * N + n0 + tx];
    __syncthreads();
    #pragma unroll
    for (int i = 0; i < 4; i++) {
        float v = tile[tx][ty + i * 8];
        unsigned short h, l;
        split_bf16(v, h, l);
        size_t o = (size_t)(n0 + ty + i * 8) * K + k0 + tx;
        Th[o] = __ushort_as_bfloat16(h);
        Tl[o] = __ushort_as_bfloat16(l);
    }
}

// ---------------- LayerNorm -> bf16 hi/lo ----------------
__global__ void __launch_bounds__(256)
ln_kernel(const float* __restrict__ x, const float* __restrict__ gam,
          const float* __restrict__ bet, __nv_bfloat16* __restrict__ oh,
          __nv_bfloat16* __restrict__ ol)
{
    int row = blockIdx.x;
    int t = threadIdx.x;
    const float4* xr = reinterpret_cast<const float4*>(x + (size_t)row * DIM);
    float4 v = xr[t];
    float s  = v.x + v.y + v.z + v.w;
    float sq = v.x*v.x + v.y*v.y + v.z*v.z + v.w*v.w;
    #pragma unroll
    for (int o = 16; o > 0; o >>= 1) {
        s  += __shfl_down_sync(0xffffffffu, s,  o);
        sq += __shfl_down_sync(0xffffffffu, sq, o);
    }
    __shared__ float ss[8], sqs[8];
    __shared__ float s_mu, s_rstd;
    int w = t >> 5, l = t & 31;
    if (l == 0) { ss[w] = s; sqs[w] = sq; }
    __syncthreads();
    if (t == 0) {
        float ts = 0.f, tq = 0.f;
        #pragma unroll
        for (int i = 0; i < 8; i++) { ts += ss[i]; tq += sqs[i]; }
        float mu  = ts * (1.0f / DIM);
        float var = tq * (1.0f / DIM) - mu * mu;
        s_mu = mu; s_rstd = rsqrtf(var + 1e-5f);
    }
    __syncthreads();
    float mu = s_mu, r = s_rstd;
    float4 g4 = reinterpret_cast<const float4*>(gam)[t];
    float4 b4 = reinterpret_cast<const float4*>(bet)[t];
    float o0 = (v.x - mu) * r * g4.x + b4.x;
    float o1 = (v.y - mu) * r * g4.y + b4.y;
    float o2 = (v.z - mu) * r * g4.z + b4.z;
    float o3 = (v.w - mu) * r * g4.w + b4.w;
    ushort4 hu, lu;
    split_bf16(o0, hu.x, lu.x); split_bf16(o1, hu.y, lu.y);
    split_bf16(o2, hu.z, lu.z); split_bf16(o3, hu.w, lu.w);
    size_t idx = (size_t)row * DIM + t * 4;
    *reinterpret_cast<ushort4*>(oh + idx) = hu;
    *reinterpret_cast<ushort4*>(ol + idx) = lu;
}

// ---------------- HMMA bf16 hi/lo split GEMM ----------------
#define GSTRIDE  80
#define GMAT     (128 * GSTRIDE)
#define GSTAGE   (4 * GMAT)
#define GEMM_SMEM (2 * GSTAGE)

__global__ void __launch_bounds__(256)
gemm_bf16_kernel(const __nv_bfloat16* __restrict__ Ah, const __nv_bfloat16* __restrict__ Al,
                 const __nv_bfloat16* __restrict__ Bh, const __nv_bfloat16* __restrict__ Bl,
                 const float* __restrict__ bias, const float* __restrict__ res,
                 float* __restrict__ Cf, __nv_bfloat16* __restrict__ Ch,
                 __nv_bfloat16* __restrict__ Cl, int M, int N, int K, int gelu_flag)
{
    extern __shared__ char smem[];
    uint32_t sb0 = smem_u32(smem);
    int tid = threadIdx.x;
    int wid = tid >> 5, lane = tid & 31;
    int warp_m = wid & 3, warp_n = wid >> 2;
    int m0 = blockIdx.y * 128, n0 = blockIdx.x * 128;

    int lrow = tid >> 1;
    int lcol = (tid & 1) * 32;
    uint32_t soff = (uint32_t)lrow * GSTRIDE + lcol;
    const char* gA_h = (const char*)(Ah + (size_t)(m0 + lrow) * K) + lcol;
    const char* gA_l = (const char*)(Al + (size_t)(m0 + lrow) * K) + lcol;
    const char* gB_h = (const char*)(Bh + (size_t)(n0 + lrow) * K) + lcol;
    const char* gB_l = (const char*)(Bl + (size_t)(n0 + lrow) * K) + lcol;

    float acc[2][8][4];
    #pragma unroll
    for (int i = 0; i < 2; i++)
        #pragma unroll
        for (int j = 0; j < 8; j++)
            #pragma unroll
            for (int q = 0; q < 4; q++) acc[i][j][q] = 0.f;

    int C = K >> 5;

    {
        uint32_t d = sb0 + soff;
        cpa16(d + 0 * GMAT, gA_h);      cpa16(d + 0 * GMAT + 16, gA_h + 16);
        cpa16(d + 1 * GMAT, gA_l);      cpa16(d + 1 * GMAT + 16, gA_l + 16);
        cpa16(d + 2 * GMAT, gB_h);      cpa16(d + 2 * GMAT + 16, gB_h + 16);
        cpa16(d + 3 * GMAT, gB_l);      cpa16(d + 3 * GMAT + 16, gB_l + 16);
        cpa_commit();
    }

    int lg = lane & 7;
    int sel = lane >> 3;
    uint32_t a_lane_off = (uint32_t)(lg + (sel & 1) * 8) * GSTRIDE + (uint32_t)(sel >> 1) * 16;
    uint32_t b_lane_off = (uint32_t)(lg + (sel >> 1) * 8) * GSTRIDE + (uint32_t)(sel & 1) * 16;

    for (int c = 0; c < C; c++) {
        if (c + 1 < C) {
            uint32_t d = sb0 + ((c + 1) & 1) * GSTAGE + soff;
            size_t go = (size_t)(c + 1) * 64;
            cpa16(d + 0 * GMAT, gA_h + go);  cpa16(d + 0 * GMAT + 16, gA_h + go + 16);
            cpa16(d + 1 * GMAT, gA_l + go);  cpa16(d + 1 * GMAT + 16, gA_l + go + 16);
            cpa16(d + 2 * GMAT, gB_h + go);  cpa16(d + 2 * GMAT + 16, gB_h + go + 16);
            cpa16(d + 3 * GMAT, gB_l + go);  cpa16(d + 3 * GMAT + 16, gB_l + go + 16);
            cpa_commit();
            asm volatile("cp.async.wait_group 1;" ::: "memory");
        } else {
            asm volatile("cp.async.wait_group 0;" ::: "memory");
        }
        __syncthreads();

        uint32_t st = sb0 + (c & 1) * GSTAGE;
        uint32_t aH = st + 0 * GMAT, aL = st + 1 * GMAT;
        uint32_t bH = st + 2 * GMAT, bL = st + 3 * GMAT;

        #pragma unroll
        for (int kk = 0; kk < 2; kk++) {
            uint32_t kb = (uint32_t)kk * 32;
            uint32_t afh[2][4], afl[2][4], bfh[8][2], bfl[8][2];
            #pragma unroll
            for (int mt = 0; mt < 2; mt++) {
                uint32_t ro = (uint32_t)(warp_m * 32 + mt * 16) * GSTRIDE + kb + a_lane_off;
                ldm_x4(afh[mt], aH + ro);
                ldm_x4(afl[mt], aL + ro);
            }
            #pragma unroll
            for (int pr = 0; pr < 4; pr++) {
                uint32_t ro = (uint32_t)(warp_n * 64 + pr * 16) * GSTRIDE + kb + b_lane_off;
                uint32_t th[4], tl[4];
                ldm_x4(th, bH + ro);
                ldm_x4(tl, bL + ro);
                bfh[pr * 2][0] = th[0]; bfh[pr * 2][1] = th[1];
                bfh[pr * 2 + 1][0] = th[2]; bfh[pr * 2 + 1][1] = th[3];
                bfl[pr * 2][0] = tl[0]; bfl[pr * 2][1] = tl[1];
                bfl[pr * 2 + 1][0] = tl[2]; bfl[pr * 2 + 1][1] = tl[3];
            }
            #pragma unroll
            for (int mt = 0; mt < 2; mt++)
                #pragma unroll
                for (int nt = 0; nt < 8; nt++) {
                    mma_bf16(acc[mt][nt], afh[mt], bfh[nt]);
                    mma_bf16(acc[mt][nt], afh[mt], bfl[nt]);
                    mma_bf16(acc[mt][nt], afl[mt], bfh[nt]);
                }
        }
        __syncthreads();
    }

    int g = lane >> 2, tig = lane & 3;
    #pragma unroll
    for (int mt = 0; mt < 2; mt++) {
        #pragma unroll
        for (int half = 0; half < 2; half++) {
            int r = m0 + warp_m * 32 + mt * 16 + g + half * 8;
            #pragma unroll
            for (int nt = 0; nt < 8; nt++) {
                int cc = n0 + warp_n * 64 + nt * 8 + tig * 2;
                float v0 = acc[mt][nt][half * 2 + 0];
                float v1 = acc[mt][nt][half * 2 + 1];
                if (bias) { v0 += bias[cc]; v1 += bias[cc + 1]; }
                if (gelu_flag) { v0 = gelu_exact(v0); v1 = gelu_exact(v1); }
                size_t o = (size_t)r * N + cc;
                if (res) {
                    float2 r2 = *reinterpret_cast<const float2*>(res + o);
                    v0 += r2.x; v1 += r2.y;
                }
                if (Cf) {
                    float2 f2 = { v0, v1 };
                    *reinterpret_cast<float2*>(Cf + o) = f2;
                } else {
                    ushort2 hu, lu;
                    split_bf16(v0, hu.x, lu.x);
                    split_bf16(v1, hu.y, lu.y);
                    *reinterpret_cast<ushort2*>(Ch + o) = hu;
                    *reinterpret_cast<ushort2*>(Cl + o) = lu;
                }
            }
        }
    }
}

// ---------------- tensor-core flash attention ----------------
// 128 queries per CTA, 8 warps (m16 each), key chunks of 128, d=64.
// All operands bf16 hi/lo split; fp32 accum; register online softmax.
#define ASTRIDE 144                     // smem row bytes (72 bf16, 64 used)
#define AMAT    (128 * ASTRIDE)         // 18432 B
#define ATT_STG (2 * AMAT)              // Q hi/lo before stages
#define ATT_STAGE_B (4 * AMAT)          // Kh,Kl,Vh,Vl
#define ATT_SMEM (ATT_STG + 2 * ATT_STAGE_B)   // 184320 B

__global__ void __launch_bounds__(256)
attn_mma_kernel(const __nv_bfloat16* __restrict__ qh,
                const __nv_bfloat16* __restrict__ ql,
                __nv_bfloat16* __restrict__ oh, __nv_bfloat16* __restrict__ ol)
{
    extern __shared__ char smem[];
    uint32_t sb = smem_u32(smem);
    int tid = threadIdx.x, lane = tid & 31, wid = tid >> 5;
    int qt = blockIdx.x, h = blockIdx.y, b = blockIdx.z;
    int q0 = b * SEQ + qt * 128;

    // ---- cp.async mapping ----
    int seg = tid & 7;                  // 16B column
    int r0  = tid >> 3;                 // 0..31
    size_t qrow = (size_t)(q0 + r0) * QKVN + h * DH;
    size_t krow = (size_t)(b * SEQ + r0) * QKVN + INNER + h * DH;
    size_t vrow = krow + INNER;
    const char* gq_h = (const char*)(qh + qrow) + seg * 16;
    const char* gq_l = (const char*)(ql + qrow) + seg * 16;
    const char* gk_h = (const char*)(qh + krow) + seg * 16;
    const char* gk_l = (const char*)(ql + krow) + seg * 16;
    const char* gv_h = (const char*)(qh + vrow) + seg * 16;
    const char* gv_l = (const char*)(ql + vrow) + seg * 16;
    uint32_t soff = (uint32_t)r0 * ASTRIDE + seg * 16;
    const size_t rowskip = (size_t)32 * QKVN * 2;     // 32 rows in bytes
    const size_t chunkskip = (size_t)128 * QKVN * 2;  // 128 rows in bytes

    // prefetch Q + chunk 0
    #pragma unroll
    for (int u = 0; u < 4; u++) {
        uint32_t so = soff + u * 32 * ASTRIDE;
        size_t go = (size_t)u * rowskip;
        cpa16(sb + 0    + so, gq_h + go);
        cpa16(sb + AMAT + so, gq_l + go);
        uint32_t st = sb + ATT_STG;
        cpa16(st + 0 * AMAT + so, gk_h + go);
        cpa16(st + 1 * AMAT + so, gk_l + go);
        cpa16(st + 2 * AMAT + so, gv_h + go);
        cpa16(st + 3 * AMAT + so, gv_l + go);
    }
    cpa_commit();
    asm volatile("cp.async.wait_group 0;" ::: "memory");
    __syncthreads();

    // ---- ldmatrix lane offsets ----
    int lg = lane & 7, sel = lane >> 3;
    uint32_t a_off = (uint32_t)(lg + (sel & 1) * 8) * ASTRIDE + (uint32_t)(sel >> 1) * 16;
    uint32_t b_off = (uint32_t)(lg + (sel >> 1) * 8) * ASTRIDE + (uint32_t)(sel & 1) * 16;

    // ---- Q fragments (held in registers for whole kernel) ----
    uint32_t qfh[4][4], qfl[4][4];
    {
        uint32_t qb = sb + (uint32_t)(wid * 16) * ASTRIDE + a_off;
        #pragma unroll
        for (int s = 0; s < 4; s++) {
            ldm_x4(qfh[s], qb + s * 32);
            ldm_x4(qfl[s], qb + AMAT + s * 32);
        }
    }

    float m0r = -INFINITY, m1r = -INFINITY, l0r = 0.f, l1r = 0.f;
    float oacc[8][4];
    #pragma unroll
    for (int i = 0; i < 8; i++)
        #pragma unroll
        for (int j = 0; j < 4; j++) oacc[i][j] = 0.f;

    for (int c = 0; c < 16; c++) {
        if (c + 1 < 16) {
            uint32_t st = sb + ATT_STG + ((c + 1) & 1) * ATT_STAGE_B;
            size_t go0 = (size_t)(c + 1) * chunkskip;
            #pragma unroll
            for (int u = 0; u < 4; u++) {
                uint32_t so = soff + u * 32 * ASTRIDE;
                size_t go = go0 + (size_t)u * rowskip;
                cpa16(st + 0 * AMAT + so, gk_h + go);
                cpa16(st + 1 * AMAT + so, gk_l + go);
                cpa16(st + 2 * AMAT + so, gv_h + go);
                cpa16(st + 3 * AMAT + so, gv_l + go);
            }
            cpa_commit();
            asm volatile("cp.async.wait_group 1;" ::: "memory");
        } else {
            asm volatile("cp.async.wait_group 0;" ::: "memory");
        }
        __syncthreads();

        uint32_t st = sb + ATT_STG + (c & 1) * ATT_STAGE_B;

        // ---- S = Q @ K^T (3-term split) ----
        float sacc[16][4];
        #pragma unroll
        for (int i = 0; i < 16; i++)
            #pragma unroll
            for (int j = 0; j < 4; j++) sacc[i][j] = 0.f;

        #pragma unroll
        for (int s = 0; s < 4; s++) {
            #pragma unroll
            for (int np = 0; np < 8; np++) {
                uint32_t ro = st + (uint32_t)(np * 16) * ASTRIDE + s * 32 + b_off;
                uint32_t th[4], tl[4];
                ldm_x4(th, ro);
                ldm_x4(tl, ro + AMAT);
                mma_bf16(sacc[2 * np],     qfh[s], th);
                mma_bf16(sacc[2 * np],     qfh[s], tl);
                mma_bf16(sacc[2 * np],     qfl[s], th);
                mma_bf16(sacc[2 * np + 1], qfh[s], th + 2);
                mma_bf16(sacc[2 * np + 1], qfh[s], tl + 2);
                mma_bf16(sacc[2 * np + 1], qfl[s], th + 2);
            }
        }

        // ---- online softmax (rows g, g+8) ----
        #pragma unroll
        for (int nt = 0; nt < 16; nt++) {
            sacc[nt][0] *= 0.125f; sacc[nt][1] *= 0.125f;
            sacc[nt][2] *= 0.125f; sacc[nt][3] *= 0.125f;
        }
        float mx0 = m0r, mx1 = m1r;
        #pragma unroll
        for (int nt = 0; nt < 16; nt++) {
            mx0 = fmaxf(mx0, fmaxf(sacc[nt][0], sacc[nt][1]));
            mx1 = fmaxf(mx1, fmaxf(sacc[nt][2], sacc[nt][3]));
        }
        mx0 = fmaxf(mx0, __shfl_xor_sync(0xffffffffu, mx0, 1));
        mx0 = fmaxf(mx0, __shfl_xor_sync(0xffffffffu, mx0, 2));
        mx1 = fmaxf(mx1, __shfl_xor_sync(0xffffffffu, mx1, 1));
        mx1 = fmaxf(mx1, __shfl_xor_sync(0xffffffffu, mx1, 2));
        float al0 = __expf(m0r - mx0);
        float al1 = __expf(m1r - mx1);
        m0r = mx0; m1r = mx1;
        float s0 = 0.f, s1 = 0.f;
        #pragma unroll
        for (int nt = 0; nt < 16; nt++) {
            float p0 = __expf(sacc[nt][0] - mx0);
            float p1 = __expf(sacc[nt][1] - mx0);
            float p2 = __expf(sacc[nt][2] - mx1);
            float p3 = __expf(sacc[nt][3] - mx1);
            sacc[nt][0] = p0; sacc[nt][1] = p1; sacc[nt][2] = p2; sacc[nt][3] = p3;
            s0 += p0 + p1; s1 += p2 + p3;
        }
        s0 += __shfl_xor_sync(0xffffffffu, s0, 1);
        s0 += __shfl_xor_sync(0xffffffffu, s0, 2);
        s1 += __shfl_xor_sync(0xffffffffu, s1, 1);
        s1 += __shfl_xor_sync(0xffffffffu, s1, 2);
        l0r = l0r * al0 + s0;
        l1r = l1r * al1 + s1;
        #pragma unroll
        for (int nt = 0; nt < 8; nt++) {
            oacc[nt][0] *= al0; oacc[nt][1] *= al0;
            oacc[nt][2] *= al1; oacc[nt][3] *= al1;
        }

        // ---- O += P @ V (3-term split, trans ldmatrix on V) ----
        #pragma unroll
        for (int s = 0; s < 8; s++) {
            uint32_t aph[4], apl[4];
            split_pack2(sacc[2*s][0],   sacc[2*s][1],   aph[0], apl[0]);
            split_pack2(sacc[2*s][2],   sacc[2*s][3],   aph[1], apl[1]);
            split_pack2(sacc[2*s+1][0], sacc[2*s+1][1], aph[2], apl[2]);
            split_pack2(sacc[2*s+1][2], sacc[2*s+1][3], aph[3], apl[3]);
            #pragma unroll
            for (int np = 0; np < 4; np++) {
                uint32_t ro = st + 2 * AMAT + (uint32_t)(s * 16) * ASTRIDE + np * 32 + a_off;
                uint32_t th[4], tl[4];
                ldm_x4_t(th, ro);
                ldm_x4_t(tl, ro + AMAT);
                mma_bf16(oacc[2 * np],     aph, th);
                mma_bf16(oacc[2 * np],     aph, tl);
                mma_bf16(oacc[2 * np],     apl, th);
                mma_bf16(oacc[2 * np + 1], aph, th + 2);
                mma_bf16(oacc[2 * np + 1], aph, tl + 2);
                mma_bf16(oacc[2 * np + 1], apl, th + 2);
            }
        }
        __syncthreads();
    }

    // ---- normalize + write hi/lo ----
    float inv0 = 1.0f / l0r, inv1 = 1.0f / l1r;
    int g = lane >> 2, tig = lane & 3;
    int row = q0 + wid * 16 + g;
    #pragma unroll
    for (int nt = 0; nt < 8; nt++) {
        int col = h * DH + nt * 8 + tig * 2;
        float v0 = oacc[nt][0] * inv0, v1 = oacc[nt][1] * inv0;
        float v2 = oacc[nt][2] * inv1, v3 = oacc[nt][3] * inv1;
        ushort2 hu, lu;
        split_bf16(v0, hu.x, lu.x); split_bf16(v1, hu.y, lu.y);
        size_t o0 = (size_t)row * DIM + col;
        *reinterpret_cast<ushort2*>(oh + o0) = hu;
        *reinterpret_cast<ushort2*>(ol + o0) = lu;
        split_bf16(v2, hu.x, lu.x); split_bf16(v3, hu.y, lu.y);
        size_t o1 = (size_t)(row + 8) * DIM + col;
        *reinterpret_cast<ushort2*>(oh + o1) = hu;
        *reinterpret_cast<ushort2*>(ol + o1) = lu;
    }
}

// ---------------- launch ----------------
extern "C" void kernel_launch(void* const* d_in, const int* in_sizes, int n_in,
                              void* d_out, int out_size)
{
    const float* x     = (const float*)d_in[0];
    const float* ln1_g = (const float*)d_in[1];
    const float* ln1_b = (const float*)d_in[2];
    const float* w_qkv = (const float*)d_in[3];
    const float* w_out = (const float*)d_in[4];
    const float* b_out = (const float*)d_in[5];
    const float* ln2_g = (const float*)d_in[6];
    const float* ln2_b = (const float*)d_in[7];
    const float* w1    = (const float*)d_in[8];
    const float* b1    = (const float*)d_in[9];
    const float* w2    = (const float*)d_in[10];
    const float* b2    = (const float*)d_in[11];
    float* out = (float*)d_out;

    __nv_bfloat16 *wqkv_h, *wqkv_l, *wout_h, *wout_l, *w1_h, *w1_l, *w2_h, *w2_l;
    __nv_bfloat16 *ah, *al, *bh, *bl, *qh, *ql;
    float *x2;
    cudaGetSymbolAddress((void**)&wqkv_h, g_wqkv_h);
    cudaGetSymbolAddress((void**)&wqkv_l, g_wqkv_l);
    cudaGetSymbolAddress((void**)&wout_h, g_wout_h);
    cudaGetSymbolAddress((void**)&wout_l, g_wout_l);
    cudaGetSymbolAddress((void**)&w1_h,   g_w1_h);
    cudaGetSymbolAddress((void**)&w1_l,   g_w1_l);
    cudaGetSymbolAddress((void**)&w2_h,   g_w2_h);
    cudaGetSymbolAddress((void**)&w2_l,   g_w2_l);
    cudaGetSymbolAddress((void**)&ah,     g_ah);
    cudaGetSymbolAddress((void**)&al,     g_al);
    cudaGetSymbolAddress((void**)&bh,     g_bh);
    cudaGetSymbolAddress((void**)&bl,     g_bl);
    cudaGetSymbolAddress((void**)&qh,     g_qh);
    cudaGetSymbolAddress((void**)&ql,     g_ql);
    cudaGetSymbolAddress((void**)&x2,     g_x2);

    cudaFuncSetAttribute(gemm_bf16_kernel, cudaFuncAttributeMaxDynamicSharedMemorySize, GEMM_SMEM);
    cudaFuncSetAttribute(attn_mma_kernel, cudaFuncAttributeMaxDynamicSharedMemorySize, ATT_SMEM);

    // weight split+transpose
    wconv_kernel<<<dim3(QKVN / 32, DIM / 32), 256>>>(w_qkv, wqkv_h, wqkv_l, DIM, QKVN);
    wconv_kernel<<<dim3(DIM / 32, INNER / 32), 256>>>(w_out, wout_h, wout_l, INNER, DIM);
    wconv_kernel<<<dim3(MLPD / 32, DIM / 32), 256>>>(w1, w1_h, w1_l, DIM, MLPD);
    wconv_kernel<<<dim3(DIM / 32, MLPD / 32), 256>>>(w2, w2_h, w2_l, MLPD, DIM);

    // 1. LN1 -> bf16 hi/lo
    ln_kernel<<<TOK, 256>>>(x, ln1_g, ln1_b, ah, al);
    // 2. qkv = h @ w_qkv -> bf16 hi/lo
    gemm_bf16_kernel<<<dim3(QKVN / 128, TOK / 128), 256, GEMM_SMEM>>>(
        ah, al, wqkv_h, wqkv_l, nullptr, nullptr, nullptr, qh, ql,
        TOK, QKVN, DIM, 0);
    // 3. attention (tensor cores) -> bf16 hi/lo
    attn_mma_kernel<<<dim3(SEQ / 128, NH, BATCH), 256, ATT_SMEM>>>(qh, ql, ah, al);
    // 4. x2 = attn @ w_out + b_out + x (fp32)
    gemm_bf16_kernel<<<dim3(DIM / 128, TOK / 128), 256, GEMM_SMEM>>>(
        ah, al, wout_h, wout_l, b_out, x, x2, nullptr, nullptr,
        TOK, DIM, INNER, 0);
    // 5. LN2 -> bf16 hi/lo
    ln_kernel<<<TOK, 256>>>(x2, ln2_g, ln2_b, ah, al);
    // 6. mlp = gelu(h @ w1 + b1) -> bf16 hi/lo
    gemm_bf16_kernel<<<dim3(MLPD / 128, TOK / 128), 256, GEMM_SMEM>>>(
        ah, al, w1_h, w1_l, b1, nullptr, nullptr, bh, bl,
        TOK, MLPD, DIM, 1);
    // 7. out = mlp @ w2 + b2 + x2 (fp32)
    gemm_bf16_kernel<<<dim3(DIM / 128, TOK / 128), 256, GEMM_SMEM>>>(
        bh, bl, w2_h, w2_l, b2, x2, out, nullptr, nullptr,
        TOK, DIM, MLPD, 0);
}

// round 6
// speedup vs baseline: 3.7758x; 1.2121x over previous
#include <cuda_runtime.h>
#include <cuda_bf16.h>
#include <cuda_fp16.h>
#include <math.h>
#include <stdint.h>

// ---------------- problem constants ----------------
#define TOK    8192
#define DIM    1024
#define INNER  1024
#define QKVN   3072
#define MLPD   4096
#define NH     16
#define DH     64
#define SEQ    2048
#define BATCH  4

// ---------------- device scratch ----------------
__device__ __half g_wqkv_h[DIM * QKVN];   // weights fp16 hi/lo, transposed [N,K]
__device__ __half g_wqkv_l[DIM * QKVN];
__device__ __half g_wout_h[INNER * DIM];
__device__ __half g_wout_l[INNER * DIM];
__device__ __half g_w1_h[DIM * MLPD];
__device__ __half g_w1_l[DIM * MLPD];
__device__ __half g_w2_h[MLPD * DIM];
__device__ __half g_w2_l[MLPD * DIM];
__device__ __half g_l16[TOK * DIM];       // LN output (fp16)
__device__ __half g_a16[TOK * DIM];       // attention output (fp16)
__device__ __half g_b16[TOK * MLPD];      // mlp intermediate (fp16)
__device__ __nv_bfloat16 g_qh[TOK * QKVN];  // qkv bf16 hi/lo (attention input)
__device__ __nv_bfloat16 g_ql[TOK * QKVN];
__device__ float g_x2 [TOK * DIM];

// ---------------- small helpers ----------------
__device__ __forceinline__ uint32_t smem_u32(const void* p) {
    uint32_t a;
    asm("{ .reg .u64 t; cvta.to.shared.u64 t, %1; cvt.u32.u64 %0, t; }" : "=r"(a) : "l"(p));
    return a;
}

__device__ __forceinline__ void split_bf16(float v, unsigned short& h, unsigned short& l) {
    __nv_bfloat16 hb = __float2bfloat16(v);
    float hf = __bfloat162float(hb);
    __nv_bfloat16 lb = __float2bfloat16(v - hf);
    h = __bfloat16_as_ushort(hb);
    l = __bfloat16_as_ushort(lb);
}
__device__ __forceinline__ void split_f16(float v, unsigned short& h, unsigned short& l) {
    __half hb = __float2half_rn(v);
    float hf = __half2float(hb);
    __half lb = __float2half_rn(v - hf);
    h = __half_as_ushort(hb);
    l = __half_as_ushort(lb);
}

// split a pair (e0->low, e1->high) into hi/lo bf16x2 registers
__device__ __forceinline__ void split_pack2(float e0, float e1, uint32_t& hi, uint32_t& lo) {
    __nv_bfloat16 h0 = __float2bfloat16(e0), h1 = __float2bfloat16(e1);
    float r0 = e0 - __bfloat162float(h0);
    float r1 = e1 - __bfloat162float(h1);
    __nv_bfloat162 hh, ll;
    hh.x = h0; hh.y = h1;
    ll.x = __float2bfloat16(r0); ll.y = __float2bfloat16(r1);
    hi = *reinterpret_cast<uint32_t*>(&hh);
    lo = *reinterpret_cast<uint32_t*>(&ll);
}

__device__ __forceinline__ void cpa16(uint32_t dst, const void* src) {
    asm volatile("cp.async.cg.shared.global [%0], [%1], 16;" :: "r"(dst), "l"(src));
}
__device__ __forceinline__ void cpa_commit() { asm volatile("cp.async.commit_group;" ::: "memory"); }

__device__ __forceinline__ void ldm_x4(uint32_t* r, uint32_t addr) {
    asm volatile("ldmatrix.sync.aligned.m8n8.x4.shared.b16 {%0,%1,%2,%3}, [%4];"
                 : "=r"(r[0]), "=r"(r[1]), "=r"(r[2]), "=r"(r[3]) : "r"(addr));
}
__device__ __forceinline__ void ldm_x4_t(uint32_t* r, uint32_t addr) {
    asm volatile("ldmatrix.sync.aligned.m8n8.x4.trans.shared.b16 {%0,%1,%2,%3}, [%4];"
                 : "=r"(r[0]), "=r"(r[1]), "=r"(r[2]), "=r"(r[3]) : "r"(addr));
}

__device__ __forceinline__ void mma_bf16(float* c, const uint32_t* a, const uint32_t* b) {
    asm volatile(
        "mma.sync.aligned.m16n8k16.row.col.f32.bf16.bf16.f32 "
        "{%0,%1,%2,%3}, {%4,%5,%6,%7}, {%8,%9}, {%0,%1,%2,%3};"
        : "+f"(c[0]), "+f"(c[1]), "+f"(c[2]), "+f"(c[3])
        : "r"(a[0]), "r"(a[1]), "r"(a[2]), "r"(a[3]), "r"(b[0]), "r"(b[1]));
}
__device__ __forceinline__ void mma_f16(float* c, const uint32_t* a, const uint32_t* b) {
    asm volatile(
        "mma.sync.aligned.m16n8k16.row.col.f32.f16.f16.f32 "
        "{%0,%1,%2,%3}, {%4,%5,%6,%7}, {%8,%9}, {%0,%1,%2,%3};"
        : "+f"(c[0]), "+f"(c[1]), "+f"(c[2]), "+f"(c[3])
        : "r"(a[0]), "r"(a[1]), "r"(a[2]), "r"(a[3]), "r"(b[0]), "r"(b[1]));
}

__device__ __forceinline__ float gelu_exact(float x) {
    return 0.5f * x * (1.0f + erff(x * 0.7071067811865475f));
}

// ---------------- weight convert + transpose: fp32 [K,N] -> fp16 hi/lo [N,K] ----------------
__global__ void __launch_bounds__(256)
wconv_kernel(const float* __restrict__ W, __half* __restrict__ Th,
             __half* __restrict__ Tl, int K, int N)
{
    __shared__ float tile[32][33];
    int n0 = blockIdx.x * 32, k0 = blockIdx.y * 32;
    int tx = threadIdx.x & 31, ty = threadIdx.x >> 5;
    #pragma unroll
    for (int i = 0; i < 4; i++)
        tile[ty + i * 8][tx] = W[(size_t)(k0 + ty + i * 8) * N + n0 + tx];
    __syncthreads();
    #pragma unroll
    for (int i = 0; i < 4; i++) {
        float v = tile[tx][ty + i * 8];
        unsigned short h, l;
        split_f16(v, h, l);
        size_t o = (size_t)(n0 + ty + i * 8) * K + k0 + tx;
        Th[o] = __ushort_as_half(h);
        Tl[o] = __ushort_as_half(l);
    }
}

// ---------------- LayerNorm -> fp16 ----------------
__global__ void __launch_bounds__(256)
ln_kernel(const float* __restrict__ x, const float* __restrict__ gam,
          const float* __restrict__ bet, __half* __restrict__ o16)
{
    int row = blockIdx.x;
    int t = threadIdx.x;
    const float4* xr = reinterpret_cast<const float4*>(x + (size_t)row * DIM);
    float4 v = xr[t];
    float s  = v.x + v.y + v.z + v.w;
    float sq = v.x*v.x + v.y*v.y + v.z*v.z + v.w*v.w;
    #pragma unroll
    for (int o = 16; o > 0; o >>= 1) {
        s  += __shfl_down_sync(0xffffffffu, s,  o);
        sq += __shfl_down_sync(0xffffffffu, sq, o);
    }
    __shared__ float ss[8], sqs[8];
    __shared__ float s_mu, s_rstd;
    int w = t >> 5, l = t & 31;
    if (l == 0) { ss[w] = s; sqs[w] = sq; }
    __syncthreads();
    if (t == 0) {
        float ts = 0.f, tq = 0.f;
        #pragma unroll
        for (int i = 0; i < 8; i++) { ts += ss[i]; tq += sqs[i]; }
        float mu  = ts * (1.0f / DIM);
        float var = tq * (1.0f / DIM) - mu * mu;
        s_mu = mu; s_rstd = rsqrtf(var + 1e-5f);
    }
    __syncthreads();
    float mu = s_mu, r = s_rstd;
    float4 g4 = reinterpret_cast<const float4*>(gam)[t];
    float4 b4 = reinterpret_cast<const float4*>(bet)[t];
    float o0 = (v.x - mu) * r * g4.x + b4.x;
    float o1 = (v.y - mu) * r * g4.y + b4.y;
    float o2 = (v.z - mu) * r * g4.z + b4.z;
    float o3 = (v.w - mu) * r * g4.w + b4.w;
    __half2 p0 = __floats2half2_rn(o0, o1);
    __half2 p1 = __floats2half2_rn(o2, o3);
    uint2 u = { *reinterpret_cast<uint32_t*>(&p0), *reinterpret_cast<uint32_t*>(&p1) };
    *reinterpret_cast<uint2*>(o16 + (size_t)row * DIM + t * 4) = u;
}

// ---------------- fp16 2-term split GEMM ----------------
// C[M,N] = A[M,K] @ Bt[N,K]^T; A fp16 (trunc), B fp16 hi+lo. fp32 accum.
// 128x128 tile, BK=32, 8 warps (4Mx2N), 3-stage cp.async pipeline.
#define GSTRIDE  80
#define GMAT     (128 * GSTRIDE)         // 10240 B
#define GSTAGE   (3 * GMAT)              // A, Bh, Bl = 30720 B
#define GEMM_SMEM (3 * GSTAGE)           // 92160 B

__global__ void __launch_bounds__(256)
gemm_f16_kernel(const __half* __restrict__ A,
                const __half* __restrict__ Bh, const __half* __restrict__ Bl,
                const float* __restrict__ bias, const float* __restrict__ res,
                float* __restrict__ Cf, __nv_bfloat16* __restrict__ Cbh,
                __nv_bfloat16* __restrict__ Cbl, __half* __restrict__ C16,
                int M, int N, int K, int gelu_flag)
{
    extern __shared__ char smem[];
    uint32_t sb0 = smem_u32(smem);
    int tid = threadIdx.x;
    int wid = tid >> 5, lane = tid & 31;
    int warp_m = wid & 3, warp_n = wid >> 2;
    int m0 = blockIdx.y * 128, n0 = blockIdx.x * 128;

    int lrow = tid >> 1;
    int lcol = (tid & 1) * 32;
    uint32_t soff = (uint32_t)lrow * GSTRIDE + lcol;
    const char* gA  = (const char*)(A  + (size_t)(m0 + lrow) * K) + lcol;
    const char* gBh = (const char*)(Bh + (size_t)(n0 + lrow) * K) + lcol;
    const char* gBl = (const char*)(Bl + (size_t)(n0 + lrow) * K) + lcol;

    float acc[2][8][4];
    #pragma unroll
    for (int i = 0; i < 2; i++)
        #pragma unroll
        for (int j = 0; j < 8; j++)
            #pragma unroll
            for (int q = 0; q < 4; q++) acc[i][j][q] = 0.f;

    int C = K >> 5;

    // prefetch chunks 0,1
    #pragma unroll
    for (int p = 0; p < 2; p++) {
        uint32_t d = sb0 + p * GSTAGE + soff;
        size_t go = (size_t)p * 64;
        cpa16(d + 0 * GMAT, gA  + go);  cpa16(d + 0 * GMAT + 16, gA  + go + 16);
        cpa16(d + 1 * GMAT, gBh + go);  cpa16(d + 1 * GMAT + 16, gBh + go + 16);
        cpa16(d + 2 * GMAT, gBl + go);  cpa16(d + 2 * GMAT + 16, gBl + go + 16);
        cpa_commit();
    }

    int lg = lane & 7;
    int sel = lane >> 3;
    uint32_t a_lane_off = (uint32_t)(lg + (sel & 1) * 8) * GSTRIDE + (uint32_t)(sel >> 1) * 16;
    uint32_t b_lane_off = (uint32_t)(lg + (sel >> 1) * 8) * GSTRIDE + (uint32_t)(sel & 1) * 16;

    int s_cur = 0;   // stage of chunk c
    for (int c = 0; c < C; c++) {
        if (c + 2 < C) {
            int sp = s_cur + 2; if (sp >= 3) sp -= 3;
            uint32_t d = sb0 + sp * GSTAGE + soff;
            size_t go = (size_t)(c + 2) * 64;
            cpa16(d + 0 * GMAT, gA  + go);  cpa16(d + 0 * GMAT + 16, gA  + go + 16);
            cpa16(d + 1 * GMAT, gBh + go);  cpa16(d + 1 * GMAT + 16, gBh + go + 16);
            cpa16(d + 2 * GMAT, gBl + go);  cpa16(d + 2 * GMAT + 16, gBl + go + 16);
        }
        cpa_commit();
        asm volatile("cp.async.wait_group 2;" ::: "memory");
        __syncthreads();

        uint32_t st = sb0 + s_cur * GSTAGE;
        uint32_t aM = st, bH = st + GMAT, bL = st + 2 * GMAT;

        #pragma unroll
        for (int kk = 0; kk < 2; kk++) {
            uint32_t kb = (uint32_t)kk * 32;
            uint32_t af[2][4], bfh[8][2], bfl[8][2];
            #pragma unroll
            for (int mt = 0; mt < 2; mt++) {
                uint32_t ro = (uint32_t)(warp_m * 32 + mt * 16) * GSTRIDE + kb + a_lane_off;
                ldm_x4(af[mt], aM + ro);
            }
            #pragma unroll
            for (int pr = 0; pr < 4; pr++) {
                uint32_t ro = (uint32_t)(warp_n * 64 + pr * 16) * GSTRIDE + kb + b_lane_off;
                uint32_t th[4], tl[4];
                ldm_x4(th, bH + ro);
                ldm_x4(tl, bL + ro);
                bfh[pr * 2][0] = th[0]; bfh[pr * 2][1] = th[1];
                bfh[pr * 2 + 1][0] = th[2]; bfh[pr * 2 + 1][1] = th[3];
                bfl[pr * 2][0] = tl[0]; bfl[pr * 2][1] = tl[1];
                bfl[pr * 2 + 1][0] = tl[2]; bfl[pr * 2 + 1][1] = tl[3];
            }
            #pragma unroll
            for (int mt = 0; mt < 2; mt++)
                #pragma unroll
                for (int nt = 0; nt < 8; nt++) {
                    mma_f16(acc[mt][nt], af[mt], bfh[nt]);
                    mma_f16(acc[mt][nt], af[mt], bfl[nt]);
                }
        }
        __syncthreads();
        if (++s_cur == 3) s_cur = 0;
    }

    int g = lane >> 2, tig = lane & 3;
    #pragma unroll
    for (int mt = 0; mt < 2; mt++) {
        #pragma unroll
        for (int half = 0; half < 2; half++) {
            int r = m0 + warp_m * 32 + mt * 16 + g + half * 8;
            #pragma unroll
            for (int nt = 0; nt < 8; nt++) {
                int cc = n0 + warp_n * 64 + nt * 8 + tig * 2;
                float v0 = acc[mt][nt][half * 2 + 0];
                float v1 = acc[mt][nt][half * 2 + 1];
                if (bias) { v0 += bias[cc]; v1 += bias[cc + 1]; }
                if (gelu_flag) { v0 = gelu_exact(v0); v1 = gelu_exact(v1); }
                size_t o = (size_t)r * N + cc;
                if (res) {
                    float2 r2 = *reinterpret_cast<const float2*>(res + o);
                    v0 += r2.x; v1 += r2.y;
                }
                if (Cf) {
                    float2 f2 = { v0, v1 };
                    *reinterpret_cast<float2*>(Cf + o) = f2;
                } else if (C16) {
                    __half2 p = __floats2half2_rn(v0, v1);
                    *reinterpret_cast<uint32_t*>(C16 + o) = *reinterpret_cast<uint32_t*>(&p);
                } else {
                    ushort2 hu, lu;
                    split_bf16(v0, hu.x, lu.x);
                    split_bf16(v1, hu.y, lu.y);
                    *reinterpret_cast<ushort2*>(Cbh + o) = hu;
                    *reinterpret_cast<ushort2*>(Cbl + o) = lu;
                }
            }
        }
    }
}

// ---------------- tensor-core flash attention (bf16 3-term) ----------------
#define ASTRIDE 144
#define AMAT    (128 * ASTRIDE)
#define ATT_STG (2 * AMAT)
#define ATT_STAGE_B (4 * AMAT)
#define ATT_SMEM (ATT_STG + 2 * ATT_STAGE_B)

__global__ void __launch_bounds__(256)
attn_mma_kernel(const __nv_bfloat16* __restrict__ qh,
                const __nv_bfloat16* __restrict__ ql,
                __half* __restrict__ o16)
{
    extern __shared__ char smem[];
    uint32_t sb = smem_u32(smem);
    int tid = threadIdx.x, lane = tid & 31, wid = tid >> 5;
    int qt = blockIdx.x, h = blockIdx.y, b = blockIdx.z;
    int q0 = b * SEQ + qt * 128;

    int seg = tid & 7;
    int r0  = tid >> 3;
    size_t qrow = (size_t)(q0 + r0) * QKVN + h * DH;
    size_t krow = (size_t)(b * SEQ + r0) * QKVN + INNER + h * DH;
    size_t vrow = krow + INNER;
    const char* gq_h = (const char*)(qh + qrow) + seg * 16;
    const char* gq_l = (const char*)(ql + qrow) + seg * 16;
    const char* gk_h = (const char*)(qh + krow) + seg * 16;
    const char* gk_l = (const char*)(ql + krow) + seg * 16;
    const char* gv_h = (const char*)(qh + vrow) + seg * 16;
    const char* gv_l = (const char*)(ql + vrow) + seg * 16;
    uint32_t soff = (uint32_t)r0 * ASTRIDE + seg * 16;
    const size_t rowskip = (size_t)32 * QKVN * 2;
    const size_t chunkskip = (size_t)128 * QKVN * 2;

    #pragma unroll
    for (int u = 0; u < 4; u++) {
        uint32_t so = soff + u * 32 * ASTRIDE;
        size_t go = (size_t)u * rowskip;
        cpa16(sb + 0    + so, gq_h + go);
        cpa16(sb + AMAT + so, gq_l + go);
        uint32_t st = sb + ATT_STG;
        cpa16(st + 0 * AMAT + so, gk_h + go);
        cpa16(st + 1 * AMAT + so, gk_l + go);
        cpa16(st + 2 * AMAT + so, gv_h + go);
        cpa16(st + 3 * AMAT + so, gv_l + go);
    }
    cpa_commit();
    asm volatile("cp.async.wait_group 0;" ::: "memory");
    __syncthreads();

    int lg = lane & 7, sel = lane >> 3;
    uint32_t a_off = (uint32_t)(lg + (sel & 1) * 8) * ASTRIDE + (uint32_t)(sel >> 1) * 16;
    uint32_t b_off = (uint32_t)(lg + (sel >> 1) * 8) * ASTRIDE + (uint32_t)(sel & 1) * 16;

    uint32_t qfh[4][4], qfl[4][4];
    {
        uint32_t qb = sb + (uint32_t)(wid * 16) * ASTRIDE + a_off;
        #pragma unroll
        for (int s = 0; s < 4; s++) {
            ldm_x4(qfh[s], qb + s * 32);
            ldm_x4(qfl[s], qb + AMAT + s * 32);
        }
    }

    float m0r = -INFINITY, m1r = -INFINITY, l0r = 0.f, l1r = 0.f;
    float oacc[8][4];
    #pragma unroll
    for (int i = 0; i < 8; i++)
        #pragma unroll
        for (int j = 0; j < 4; j++) oacc[i][j] = 0.f;

    for (int c = 0; c < 16; c++) {
        if (c + 1 < 16) {
            uint32_t st = sb + ATT_STG + ((c + 1) & 1) * ATT_STAGE_B;
            size_t go0 = (size_t)(c + 1) * chunkskip;
            #pragma unroll
            for (int u = 0; u < 4; u++) {
                uint32_t so = soff + u * 32 * ASTRIDE;
                size_t go = go0 + (size_t)u * rowskip;
                cpa16(st + 0 * AMAT + so, gk_h + go);
                cpa16(st + 1 * AMAT + so, gk_l + go);
                cpa16(st + 2 * AMAT + so, gv_h + go);
                cpa16(st + 3 * AMAT + so, gv_l + go);
            }
            cpa_commit();
            asm volatile("cp.async.wait_group 1;" ::: "memory");
        } else {
            asm volatile("cp.async.wait_group 0;" ::: "memory");
        }
        __syncthreads();

        uint32_t st = sb + ATT_STG + (c & 1) * ATT_STAGE_B;

        float sacc[16][4];
        #pragma unroll
        for (int i = 0; i < 16; i++)
            #pragma unroll
            for (int j = 0; j < 4; j++) sacc[i][j] = 0.f;

        #pragma unroll
        for (int s = 0; s < 4; s++) {
            #pragma unroll
            for (int np = 0; np < 8; np++) {
                uint32_t ro = st + (uint32_t)(np * 16) * ASTRIDE + s * 32 + b_off;
                uint32_t th[4], tl[4];
                ldm_x4(th, ro);
                ldm_x4(tl, ro + AMAT);
                mma_bf16(sacc[2 * np],     qfh[s], th);
                mma_bf16(sacc[2 * np],     qfh[s], tl);
                mma_bf16(sacc[2 * np],     qfl[s], th);
                mma_bf16(sacc[2 * np + 1], qfh[s], th + 2);
                mma_bf16(sacc[2 * np + 1], qfh[s], tl + 2);
                mma_bf16(sacc[2 * np + 1], qfl[s], th + 2);
            }
        }

        #pragma unroll
        for (int nt = 0; nt < 16; nt++) {
            sacc[nt][0] *= 0.125f; sacc[nt][1] *= 0.125f;
            sacc[nt][2] *= 0.125f; sacc[nt][3] *= 0.125f;
        }
        float mx0 = m0r, mx1 = m1r;
        #pragma unroll
        for (int nt = 0; nt < 16; nt++) {
            mx0 = fmaxf(mx0, fmaxf(sacc[nt][0], sacc[nt][1]));
            mx1 = fmaxf(mx1, fmaxf(sacc[nt][2], sacc[nt][3]));
        }
        mx0 = fmaxf(mx0, __shfl_xor_sync(0xffffffffu, mx0, 1));
        mx0 = fmaxf(mx0, __shfl_xor_sync(0xffffffffu, mx0, 2));
        mx1 = fmaxf(mx1, __shfl_xor_sync(0xffffffffu, mx1, 1));
        mx1 = fmaxf(mx1, __shfl_xor_sync(0xffffffffu, mx1, 2));
        float al0 = __expf(m0r - mx0);
        float al1 = __expf(m1r - mx1);
        m0r = mx0; m1r = mx1;
        float s0 = 0.f, s1 = 0.f;
        #pragma unroll
        for (int nt = 0; nt < 16; nt++) {
            float p0 = __expf(sacc[nt][0] - mx0);
            float p1 = __expf(sacc[nt][1] - mx0);
            float p2 = __expf(sacc[nt][2] - mx1);
            float p3 = __expf(sacc[nt][3] - mx1);
            sacc[nt][0] = p0; sacc[nt][1] = p1; sacc[nt][2] = p2; sacc[nt][3] = p3;
            s0 += p0 + p1; s1 += p2 + p3;
        }
        s0 += __shfl_xor_sync(0xffffffffu, s0, 1);
        s0 += __shfl_xor_sync(0xffffffffu, s0, 2);
        s1 += __shfl_xor_sync(0xffffffffu, s1, 1);
        s1 += __shfl_xor_sync(0xffffffffu, s1, 2);
        l0r = l0r * al0 + s0;
        l1r = l1r * al1 + s1;
        #pragma unroll
        for (int nt = 0; nt < 8; nt++) {
            oacc[nt][0] *= al0; oacc[nt][1] *= al0;
            oacc[nt][2] *= al1; oacc[nt][3] *= al1;
        }

        #pragma unroll
        for (int s = 0; s < 8; s++) {
            uint32_t aph[4], apl[4];
            split_pack2(sacc[2*s][0],   sacc[2*s][1],   aph[0], apl[0]);
            split_pack2(sacc[2*s][2],   sacc[2*s][3],   aph[1], apl[1]);
            split_pack2(sacc[2*s+1][0], sacc[2*s+1][1], aph[2], apl[2]);
            split_pack2(sacc[2*s+1][2], sacc[2*s+1][3], aph[3], apl[3]);
            #pragma unroll
            for (int np = 0; np < 4; np++) {
                uint32_t ro = st + 2 * AMAT + (uint32_t)(s * 16) * ASTRIDE + np * 32 + a_off;
                uint32_t th[4], tl[4];
                ldm_x4_t(th, ro);
                ldm_x4_t(tl, ro + AMAT);
                mma_bf16(oacc[2 * np],     aph, th);
                mma_bf16(oacc[2 * np],     aph, tl);
                mma_bf16(oacc[2 * np],     apl, th);
                mma_bf16(oacc[2 * np + 1], aph, th + 2);
                mma_bf16(oacc[2 * np + 1], aph, tl + 2);
                mma_bf16(oacc[2 * np + 1], apl, th + 2);
            }
        }
        __syncthreads();
    }

    float inv0 = 1.0f / l0r, inv1 = 1.0f / l1r;
    int g = lane >> 2, tig = lane & 3;
    int row = q0 + wid * 16 + g;
    #pragma unroll
    for (int nt = 0; nt < 8; nt++) {
        int col = h * DH + nt * 8 + tig * 2;
        __half2 p0 = __floats2half2_rn(oacc[nt][0] * inv0, oacc[nt][1] * inv0);
        __half2 p1 = __floats2half2_rn(oacc[nt][2] * inv1, oacc[nt][3] * inv1);
        *reinterpret_cast<uint32_t*>(o16 + (size_t)row * DIM + col) =
            *reinterpret_cast<uint32_t*>(&p0);
        *reinterpret_cast<uint32_t*>(o16 + (size_t)(row + 8) * DIM + col) =
            *reinterpret_cast<uint32_t*>(&p1);
    }
}

// ---------------- launch ----------------
extern "C" void kernel_launch(void* const* d_in, const int* in_sizes, int n_in,
                              void* d_out, int out_size)
{
    const float* x     = (const float*)d_in[0];
    const float* ln1_g = (const float*)d_in[1];
    const float* ln1_b = (const float*)d_in[2];
    const float* w_qkv = (const float*)d_in[3];
    const float* w_out = (const float*)d_in[4];
    const float* b_out = (const float*)d_in[5];
    const float* ln2_g = (const float*)d_in[6];
    const float* ln2_b = (const float*)d_in[7];
    const float* w1    = (const float*)d_in[8];
    const float* b1    = (const float*)d_in[9];
    const float* w2    = (const float*)d_in[10];
    const float* b2    = (const float*)d_in[11];
    float* out = (float*)d_out;

    __half *wqkv_h, *wqkv_l, *wout_h, *wout_l, *w1_h, *w1_l, *w2_h, *w2_l;
    __half *l16, *a16, *b16;
    __nv_bfloat16 *qh, *ql;
    float *x2;
    cudaGetSymbolAddress((void**)&wqkv_h, g_wqkv_h);
    cudaGetSymbolAddress((void**)&wqkv_l, g_wqkv_l);
    cudaGetSymbolAddress((void**)&wout_h, g_wout_h);
    cudaGetSymbolAddress((void**)&wout_l, g_wout_l);
    cudaGetSymbolAddress((void**)&w1_h,   g_w1_h);
    cudaGetSymbolAddress((void**)&w1_l,   g_w1_l);
    cudaGetSymbolAddress((void**)&w2_h,   g_w2_h);
    cudaGetSymbolAddress((void**)&w2_l,   g_w2_l);
    cudaGetSymbolAddress((void**)&l16,    g_l16);
    cudaGetSymbolAddress((void**)&a16,    g_a16);
    cudaGetSymbolAddress((void**)&b16,    g_b16);
    cudaGetSymbolAddress((void**)&qh,     g_qh);
    cudaGetSymbolAddress((void**)&ql,     g_ql);
    cudaGetSymbolAddress((void**)&x2,     g_x2);

    cudaFuncSetAttribute(gemm_f16_kernel, cudaFuncAttributeMaxDynamicSharedMemorySize, GEMM_SMEM);
    cudaFuncSetAttribute(attn_mma_kernel, cudaFuncAttributeMaxDynamicSharedMemorySize, ATT_SMEM);

    // weight split+transpose (fp16 hi/lo)
    wconv_kernel<<<dim3(QKVN / 32, DIM / 32), 256>>>(w_qkv, wqkv_h, wqkv_l, DIM, QKVN);
    wconv_kernel<<<dim3(DIM / 32, INNER / 32), 256>>>(w_out, wout_h, wout_l, INNER, DIM);
    wconv_kernel<<<dim3(MLPD / 32, DIM / 32), 256>>>(w1, w1_h, w1_l, DIM, MLPD);
    wconv_kernel<<<dim3(DIM / 32, MLPD / 32), 256>>>(w2, w2_h, w2_l, MLPD, DIM);

    // 1. LN1 -> fp16
    ln_kernel<<<TOK, 256>>>(x, ln1_g, ln1_b, l16);
    // 2. qkv = h @ w_qkv -> bf16 hi/lo (attention input)
    gemm_f16_kernel<<<dim3(QKVN / 128, TOK / 128), 256, GEMM_SMEM>>>(
        l16, wqkv_h, wqkv_l, nullptr, nullptr, nullptr, qh, ql, nullptr,
        TOK, QKVN, DIM, 0);
    // 3. attention (bf16 3-term) -> fp16
    attn_mma_kernel<<<dim3(SEQ / 128, NH, BATCH), 256, ATT_SMEM>>>(qh, ql, a16);
    // 4. x2 = attn @ w_out + b_out + x (fp32)
    gemm_f16_kernel<<<dim3(DIM / 128, TOK / 128), 256, GEMM_SMEM>>>(
        a16, wout_h, wout_l, b_out, x, x2, nullptr, nullptr, nullptr,
        TOK, DIM, INNER, 0);
    // 5. LN2 -> fp16
    ln_kernel<<<TOK, 256>>>(x2, ln2_g, ln2_b, l16);
    // 6. mlp = gelu(h @ w1 + b1) -> fp16
    gemm_f16_kernel<<<dim3(MLPD / 128, TOK / 128), 256, GEMM_SMEM>>>(
        l16, w1_h, w1_l, b1, nullptr, nullptr, nullptr, nullptr, b16,
        TOK, MLPD, DIM, 1);
    // 7. out = mlp @ w2 + b2 + x2 (fp32)
    gemm_f16_kernel<<<dim3(DIM / 128, TOK / 128), 256, GEMM_SMEM>>>(
        b16, w2_h, w2_l, b2, x2, out, nullptr, nullptr, nullptr,
        TOK, DIM, MLPD, 0);
}